// round 2
// baseline (speedup 1.0000x reference)
#include <cuda_runtime.h>
#include <math.h>
#include <stdint.h>

#define NF 96
#define GD 12
#define K2T 9
#define BN 4
#define HH 128
#define WW 128
#define HWSZ (HH*WW)

// ---------------- scratch (device globals; no runtime allocation) ------------
__device__ float g_t1[BN*NF*HWSZ];            // oc1 out, later c1 out
__device__ float g_t2[BN*NF*HWSZ];            // oc3 out
__device__ float g_e1[BN*NF*64*64];           // e1 out
__device__ float g_d1[BN*NF*64*64];           // d1 out
__device__ float g_off[BN*2*GD*K2T*HWSZ];     // offset conv out (216 ch)
__device__ float g_S[BN*NF*K2T*HWSZ];         // DCN sampled tensor (864 "ch")

// ---------------- tf32 helpers ------------------------------------------------
__device__ __forceinline__ float cvt_tf32(float x) {
    uint32_t r;
    asm("cvt.rna.tf32.f32 %0, %1;" : "=r"(r) : "f"(x));
    return __uint_as_float(r);
}
__device__ __forceinline__ void mma_tf32(float* d, const uint32_t* a,
                                         const uint32_t* b, const float* c) {
    asm volatile(
        "mma.sync.aligned.m16n8k8.row.col.f32.tf32.tf32.f32 "
        "{%0,%1,%2,%3},{%4,%5,%6,%7},{%8,%9},{%10,%11,%12,%13};"
        : "=f"(d[0]), "=f"(d[1]), "=f"(d[2]), "=f"(d[3])
        : "r"(a[0]), "r"(a[1]), "r"(a[2]), "r"(a[3]),
          "r"(b[0]), "r"(b[1]),
          "f"(c[0]), "f"(c[1]), "f"(c[2]), "f"(c[3]));
}

// ---------------- fp32 generic 3x3 stride-1 conv (oc1, oc3 only) --------------
__global__ __launch_bounds__(256) void conv3x3_s1(
    const float* __restrict__ inA, int cinA,
    const float* __restrict__ inB, int cinB,
    const float* __restrict__ w, const float* __restrict__ bias,
    float* __restrict__ out, int cout, int flags)
{
    const int tid = threadIdx.x;
    const int tx = tid & 15;
    const int ty = tid >> 4;
    const int x0 = (blockIdx.x & 1) * 64;
    const int y0 = (blockIdx.x >> 1) * 16;
    const int ocb = blockIdx.y * 8;
    const int n = blockIdx.z;
    const int cin = cinA + cinB;

    __shared__ float sIn[4][18][67];
    __shared__ float sW[8][4][9];

    float acc[8][4];
#pragma unroll
    for (int o = 0; o < 8; o++)
#pragma unroll
        for (int j = 0; j < 4; j++) acc[o][j] = 0.f;

    for (int ic0 = 0; ic0 < cin; ic0 += 4) {
        __syncthreads();
        for (int idx = tid; idx < 4*18*66; idx += 256) {
            int ic = idx / (18*66);
            int r  = (idx / 66) % 18;
            int c  = idx % 66;
            int gy = y0 - 1 + r;
            int gx = x0 - 1 + c;
            float v = 0.f;
            if ((unsigned)gy < (unsigned)HH && (unsigned)gx < (unsigned)WW) {
                int icg = ic0 + ic;
                const float* p = (icg < cinA)
                    ? (inA + ((size_t)(n*cinA + icg)*HH + gy)*WW + gx)
                    : (inB + ((size_t)(n*cinB + (icg - cinA))*HH + gy)*WW + gx);
                v = *p;
            }
            sIn[ic][r][c] = v;
        }
        for (int idx = tid; idx < 8*4*9; idx += 256) {
            int o  = idx / 36;
            int ic = (idx / 9) % 4;
            int t  = idx % 9;
            sW[o][ic][t] = w[((size_t)(ocb + o)*cin + ic0 + ic)*9 + t];
        }
        __syncthreads();

#pragma unroll
        for (int ic = 0; ic < 4; ic++) {
#pragma unroll
            for (int dy = 0; dy < 3; dy++) {
                float v[6];
#pragma unroll
                for (int j = 0; j < 6; j++) v[j] = sIn[ic][ty + dy][4*tx + j];
#pragma unroll
                for (int dx = 0; dx < 3; dx++) {
                    float wv[8];
#pragma unroll
                    for (int o = 0; o < 8; o++) wv[o] = sW[o][ic][dy*3 + dx];
#pragma unroll
                    for (int j = 0; j < 4; j++) {
                        float xv = v[j + dx];
#pragma unroll
                        for (int o = 0; o < 8; o++)
                            acc[o][j] = fmaf(wv[o], xv, acc[o][j]);
                    }
                }
            }
        }
    }

    const int y = y0 + ty;
#pragma unroll
    for (int o = 0; o < 8; o++) {
        float bv = bias[ocb + o];
#pragma unroll
        for (int j = 0; j < 4; j++) {
            float v = acc[o][j] + bv;
            if (flags & 1) v = (v >= 0.f) ? v : 0.1f * v;
            size_t oi = ((size_t)(n*cout + ocb + o)*HH + y)*WW + (x0 + 4*tx + j);
            if (flags & 2) out[oi] += v; else out[oi] = v;
        }
    }
}

// ---------------- TF32 implicit-GEMM 3x3 stride-1 conv ------------------------
// CTA: 32 oc x 128 px (one image row). 8 warps, each 16 oc x 32 px.
// grid: (128 rows, ceil(cout/32), B).  flags: bit0 LReLU, bit1 add-into-out.
__global__ __launch_bounds__(256) void conv3x3_tf32(
    const float* __restrict__ inA, int cinA,
    const float* __restrict__ inB, int cinB,
    const float* __restrict__ w, const float* __restrict__ bias,
    float* __restrict__ out, int cout, int flags)
{
    const int tid  = threadIdx.x;
    const int wid  = tid >> 5;
    const int lane = tid & 31;
    const int gid  = lane >> 2;     // 0..7
    const int tig  = lane & 3;      // 0..3
    const int y    = blockIdx.x;
    const int ocb  = blockIdx.y * 32;
    const int n    = blockIdx.z;
    const int cin  = cinA + cinB;
    const int warpM = (wid & 1) * 16;
    const int warpN = (wid >> 1) * 32;

    __shared__ float sIn[3][8][132];   // rows y-1..y+1, 8 ic, x_in in [-1,128] at idx x+1
    __shared__ float sW[9][8][33];     // [tap][k(ic)][oc]

    const int oc0 = ocb + warpM + gid;
    const int oc1 = oc0 + 8;
    float bv0 = (oc0 < cout) ? bias[oc0] : 0.f;
    float bv1 = (oc1 < cout) ? bias[oc1] : 0.f;

    float acc[4][4];
#pragma unroll
    for (int f = 0; f < 4; f++) {
        acc[f][0] = bv0; acc[f][1] = bv0;
        acc[f][2] = bv1; acc[f][3] = bv1;
    }

    for (int ic0 = 0; ic0 < cin; ic0 += 8) {
        __syncthreads();
        // stage input rows (3 x 8 x 130)
        for (int idx = tid; idx < 3*8*130; idx += 256) {
            int r   = idx / (8*130);
            int rem = idx % (8*130);
            int ic  = rem / 130;
            int xx  = rem % 130;         // x_in = xx - 1
            int gy  = y - 1 + r;
            int gx  = xx - 1;
            float v = 0.f;
            int icg = ic0 + ic;
            if ((unsigned)gy < (unsigned)HH && (unsigned)gx < (unsigned)WW) {
                const float* p = (icg < cinA)
                    ? (inA + ((size_t)(n*cinA + icg)*HH + gy)*WW + gx)
                    : (inB + ((size_t)(n*cinB + (icg - cinA))*HH + gy)*WW + gx);
                v = *p;
            }
            sIn[r][ic][xx] = cvt_tf32(v);
        }
        // stage weights (9 x 8 x 32)
        for (int idx = tid; idx < 9*8*32; idx += 256) {
            int t   = idx >> 8;          // tap
            int rem = idx & 255;
            int ic  = rem >> 5;
            int oc  = rem & 31;
            float v = 0.f;
            int icg = ic0 + ic, ocg = ocb + oc;
            if (ocg < cout) v = w[((size_t)ocg*cin + icg)*9 + t];
            sW[t][ic][oc] = cvt_tf32(v);
        }
        __syncthreads();

#pragma unroll
        for (int tap = 0; tap < 9; tap++) {
            const int dy = tap / 3, dx = tap % 3;
            uint32_t a[4];
            a[0] = __float_as_uint(sW[tap][tig    ][warpM + gid    ]);
            a[1] = __float_as_uint(sW[tap][tig    ][warpM + gid + 8]);
            a[2] = __float_as_uint(sW[tap][tig + 4][warpM + gid    ]);
            a[3] = __float_as_uint(sW[tap][tig + 4][warpM + gid + 8]);
#pragma unroll
            for (int f = 0; f < 4; f++) {
                const int xx = warpN + f*8 + gid + dx;   // = x_in + 1
                uint32_t b[2];
                b[0] = __float_as_uint(sIn[dy][tig    ][xx]);
                b[1] = __float_as_uint(sIn[dy][tig + 4][xx]);
                mma_tf32(acc[f], a, b, acc[f]);
            }
        }
    }

    // epilogue
#pragma unroll
    for (int f = 0; f < 4; f++) {
        const int px = warpN + f*8 + tig*2;
#pragma unroll
        for (int half = 0; half < 2; half++) {
            int oc = half ? oc1 : oc0;
            if (oc >= cout) continue;
            float v0 = acc[f][half*2 + 0];
            float v1 = acc[f][half*2 + 1];
            if (flags & 1) {
                v0 = (v0 >= 0.f) ? v0 : 0.1f*v0;
                v1 = (v1 >= 0.f) ? v1 : 0.1f*v1;
            }
            size_t oi = ((size_t)(n*cout + oc)*HH + y)*WW + px;
            if (flags & 2) { out[oi] += v0; out[oi + 1] += v1; }
            else           { out[oi]  = v0; out[oi + 1]  = v1; }
        }
    }
}

// ---------------- TF32 GEMM for DCN 1x1: out[96,HW] = W[96,864] * S[864,HW] ---
__global__ __launch_bounds__(256) void gemm1x1_tf32(
    const float* __restrict__ S, const float* __restrict__ w,
    const float* __restrict__ bias, float* __restrict__ out)
{
    const int tid  = threadIdx.x;
    const int wid  = tid >> 5;
    const int lane = tid & 31;
    const int gid  = lane >> 2;
    const int tig  = lane & 3;
    const int p0   = blockIdx.x * 128;
    const int ocb  = blockIdx.y * 32;
    const int n    = blockIdx.z;
    const int CIN  = NF * K2T;   // 864
    const int warpM = (wid & 1) * 16;
    const int warpN = (wid >> 1) * 32;

    __shared__ float sIn[8][132];
    __shared__ float sW[8][33];

    const int oc0 = ocb + warpM + gid;
    const int oc1 = oc0 + 8;
    float bv0 = bias[oc0], bv1 = bias[oc1];

    float acc[4][4];
#pragma unroll
    for (int f = 0; f < 4; f++) {
        acc[f][0] = bv0; acc[f][1] = bv0;
        acc[f][2] = bv1; acc[f][3] = bv1;
    }

    for (int k0 = 0; k0 < CIN; k0 += 8) {
        __syncthreads();
        {
            // 8 x 128 input slab
            int k = tid >> 5, rem = (tid & 31);
#pragma unroll
            for (int rep = 0; rep < 4; rep++) {
                int px = rem + rep*32;
                sIn[k][px] = cvt_tf32(S[((size_t)(n*CIN + k0 + k))*HWSZ + p0 + px]);
            }
            // 8 x 32 weights
            int kw = tid >> 5, ocw = tid & 31;
            sW[kw][ocw] = cvt_tf32(w[(size_t)(ocb + ocw)*CIN + k0 + kw]);
        }
        __syncthreads();

        uint32_t a[4];
        a[0] = __float_as_uint(sW[tig    ][warpM + gid    ]);
        a[1] = __float_as_uint(sW[tig    ][warpM + gid + 8]);
        a[2] = __float_as_uint(sW[tig + 4][warpM + gid    ]);
        a[3] = __float_as_uint(sW[tig + 4][warpM + gid + 8]);
#pragma unroll
        for (int f = 0; f < 4; f++) {
            const int px = warpN + f*8 + gid;
            uint32_t b[2];
            b[0] = __float_as_uint(sIn[tig    ][px]);
            b[1] = __float_as_uint(sIn[tig + 4][px]);
            mma_tf32(acc[f], a, b, acc[f]);
        }
    }

#pragma unroll
    for (int f = 0; f < 4; f++) {
        const int px = p0 + warpN + f*8 + tig*2;
        out[((size_t)(n*NF + oc0))*HWSZ + px    ] = acc[f][0];
        out[((size_t)(n*NF + oc0))*HWSZ + px + 1] = acc[f][1];
        out[((size_t)(n*NF + oc1))*HWSZ + px    ] = acc[f][2];
        out[((size_t)(n*NF + oc1))*HWSZ + px + 1] = acc[f][3];
    }
}

// ---------------- 3x3 stride-2 conv (SAME: pad_lo=0, pad_hi=1), fp32 ----------
template<int OCB>
__global__ __launch_bounds__(256) void conv3x3_s2(
    const float* __restrict__ in, int Hin,
    const float* __restrict__ w, const float* __restrict__ bias,
    float* __restrict__ out, float* __restrict__ out_q, int flags)
{
    const int tid = threadIdx.x;
    const int tx = tid & 15;
    const int ty = tid >> 4;
    const int Hout = Hin >> 1;
    const int tilesX = Hout >> 4;
    const int x0 = (blockIdx.x % tilesX) * 16;
    const int y0 = (blockIdx.x / tilesX) * 16;
    const int ocb = blockIdx.y * OCB;
    const int n = blockIdx.z;

    __shared__ float sIn[2][33][34];
    __shared__ float sW[OCB][2][9];

    float acc[OCB];
#pragma unroll
    for (int o = 0; o < OCB; o++) acc[o] = 0.f;

    for (int ic0 = 0; ic0 < NF; ic0 += 2) {
        __syncthreads();
        for (int idx = tid; idx < 2*33*33; idx += 256) {
            int ic = idx / (33*33);
            int r  = (idx / 33) % 33;
            int c  = idx % 33;
            int gy = 2*y0 + r;
            int gx = 2*x0 + c;
            float v = 0.f;
            if (gy < Hin && gx < Hin) {
                v = in[((size_t)(n*NF + ic0 + ic)*Hin + gy)*Hin + gx];
            }
            sIn[ic][r][c] = v;
        }
        for (int idx = tid; idx < OCB*2*9; idx += 256) {
            int o  = idx / 18;
            int ic = (idx / 9) % 2;
            int t  = idx % 9;
            sW[o][ic][t] = w[((size_t)(ocb + o)*NF + ic0 + ic)*9 + t];
        }
        __syncthreads();

#pragma unroll
        for (int ic = 0; ic < 2; ic++) {
#pragma unroll
            for (int dy = 0; dy < 3; dy++) {
#pragma unroll
                for (int dx = 0; dx < 3; dx++) {
                    float xv = sIn[ic][2*ty + dy][2*tx + dx];
#pragma unroll
                    for (int o = 0; o < OCB; o++)
                        acc[o] = fmaf(sW[o][ic][dy*3 + dx], xv, acc[o]);
                }
            }
        }
    }

#pragma unroll
    for (int o = 0; o < OCB; o++) {
        float v = acc[o] + bias[ocb + o];
        if (flags & 1) v = (v >= 0.f) ? v : 0.1f * v;
        size_t oi = ((size_t)(n*NF + ocb + o)*Hout + (y0 + ty))*Hout + (x0 + tx);
        out[oi] = v;
        if (out_q) out_q[oi] = rintf(v);   // round half to even == jnp.round
    }
}

// ---------------- 3x3 stride-2 transpose conv (2x upsample), fp32 -------------
template<int OCB>
__global__ __launch_bounds__(256) void deconv3x3_x2(
    const float* __restrict__ in, int Hin,
    const float* __restrict__ w, const float* __restrict__ bias,
    float* __restrict__ out, int flags)
{
    const int tid = threadIdx.x;
    const int tx = tid & 15;
    const int ty = tid >> 4;
    const int Hout = Hin * 2;
    const int tilesX = Hout >> 5;
    const int tX = blockIdx.x % tilesX;
    const int tY = blockIdx.x / tilesX;
    const int xin0 = tX * 16, yin0 = tY * 16;
    const int x0o = tX * 32, y0o = tY * 32;
    const int ocb = blockIdx.y * OCB;
    const int n = blockIdx.z;

    __shared__ float sIn[4][17][18];
    __shared__ float sW[OCB][4][9];

    float aEE[OCB], aEO[OCB], aOE[OCB], aOO[OCB];
#pragma unroll
    for (int o = 0; o < OCB; o++) { aEE[o]=0.f; aEO[o]=0.f; aOE[o]=0.f; aOO[o]=0.f; }

    for (int ic0 = 0; ic0 < NF; ic0 += 4) {
        __syncthreads();
        for (int idx = tid; idx < 4*17*17; idx += 256) {
            int ic = idx / (17*17);
            int r  = (idx / 17) % 17;
            int c  = idx % 17;
            int gy = yin0 - 1 + r;
            int gx = xin0 - 1 + c;
            float v = 0.f;
            if ((unsigned)gy < (unsigned)Hin && (unsigned)gx < (unsigned)Hin) {
                v = in[((size_t)(n*NF + ic0 + ic)*Hin + gy)*Hin + gx];
            }
            sIn[ic][r][c] = v;
        }
        for (int idx = tid; idx < OCB*4*9; idx += 256) {
            int o  = idx / 36;
            int ic = (idx / 9) % 4;
            int t  = idx % 9;
            sW[o][ic][t] = w[((size_t)(ocb + o)*NF + ic0 + ic)*9 + t];
        }
        __syncthreads();

#pragma unroll
        for (int ic = 0; ic < 4; ic++) {
            float v00 = sIn[ic][ty    ][tx    ];
            float v01 = sIn[ic][ty    ][tx + 1];
            float v10 = sIn[ic][ty + 1][tx    ];
            float v11 = sIn[ic][ty + 1][tx + 1];
#pragma unroll
            for (int o = 0; o < OCB; o++) {
                const float* wp = &sW[o][ic][0];
                aEE[o] = fmaf(wp[0], v00, aEE[o]);
                aEE[o] = fmaf(wp[2], v01, aEE[o]);
                aEE[o] = fmaf(wp[6], v10, aEE[o]);
                aEE[o] = fmaf(wp[8], v11, aEE[o]);
                aEO[o] = fmaf(wp[1], v01, aEO[o]);
                aEO[o] = fmaf(wp[7], v11, aEO[o]);
                aOE[o] = fmaf(wp[3], v10, aOE[o]);
                aOE[o] = fmaf(wp[5], v11, aOE[o]);
                aOO[o] = fmaf(wp[4], v11, aOO[o]);
            }
        }
    }

    const int ye = y0o + 2*ty, xe = x0o + 2*tx;
#pragma unroll
    for (int o = 0; o < OCB; o++) {
        float bv = bias[ocb + o];
        float vEE = aEE[o] + bv, vEO = aEO[o] + bv, vOE = aOE[o] + bv, vOO = aOO[o] + bv;
        if (flags & 1) {
            vEE = (vEE >= 0.f) ? vEE : 0.1f*vEE;
            vEO = (vEO >= 0.f) ? vEO : 0.1f*vEO;
            vOE = (vOE >= 0.f) ? vOE : 0.1f*vOE;
            vOO = (vOO >= 0.f) ? vOO : 0.1f*vOO;
        }
        size_t base = ((size_t)(n*NF + ocb + o)*Hout + ye)*Hout + xe;
        out[base]            = vEE;
        out[base + 1]        = vEO;
        out[base + Hout]     = vOE;
        out[base + Hout + 1] = vOO;
    }
}

// ---------------- DCNv1 bilinear sampling -------------------------------------
__global__ __launch_bounds__(256) void dcn_sample(
    const float* __restrict__ ref, const float* __restrict__ off,
    float* __restrict__ S)
{
    int idx = blockIdx.x * 256 + threadIdx.x;
    if (idx >= BN*GD*K2T*HWSZ) return;
    int p = idx & (HWSZ - 1);
    int t = idx >> 14;
    int k = t % 9;  t /= 9;
    int g = t % GD;
    int n = t / GD;
    int y = p >> 7, x = p & 127;

    int offc = (g*9 + k)*2;
    float dy = off[((size_t)(n*2*GD*K2T + offc    ))*HWSZ + p];
    float dx = off[((size_t)(n*2*GD*K2T + offc + 1))*HWSZ + p];
    float py = (float)y + (float)(k/3 - 1) + dy;
    float px = (float)x + (float)(k%3 - 1) + dx;
    float fy = floorf(py), fx = floorf(px);
    float wy = py - fy, wx = px - fx;
    int iy = (int)fy, ix = (int)fx;

    float wgt[4]; int ofs[4];
#pragma unroll
    for (int r = 0; r < 2; r++) {
#pragma unroll
        for (int c = 0; c < 2; c++) {
            int yy = iy + r, xx = ix + c;
            bool val = ((unsigned)yy < (unsigned)HH) && ((unsigned)xx < (unsigned)WW);
            float wv = (r ? wy : 1.f - wy) * (c ? wx : 1.f - wx);
            wgt[r*2 + c] = val ? wv : 0.f;
            ofs[r*2 + c] = val ? (yy*WW + xx) : 0;
        }
    }

    const float* base = ref + (size_t)(n*NF + g*8)*HWSZ;
    float* so = S + ((size_t)(n*NF + g*8)*9 + k)*HWSZ + p;
#pragma unroll
    for (int c = 0; c < 8; c++) {
        const float* bp = base + (size_t)c*HWSZ;
        float s = wgt[0]*bp[ofs[0]] + wgt[1]*bp[ofs[1]]
                + wgt[2]*bp[ofs[2]] + wgt[3]*bp[ofs[3]];
        so[(size_t)c*9*HWSZ] = s;
    }
}

// ------------------------------ launch ---------------------------------------
extern "C" void kernel_launch(void* const* d_in, const int* in_sizes, int n_in,
                              void* d_out, int out_size)
{
    const float* ref   = (const float*)d_in[0];
    const float* inp   = (const float*)d_in[1];
    const float* w_oc1 = (const float*)d_in[2];  const float* b_oc1 = (const float*)d_in[3];
    const float* w_oc3 = (const float*)d_in[4];  const float* b_oc3 = (const float*)d_in[5];
    const float* w_e1  = (const float*)d_in[6];  const float* b_e1  = (const float*)d_in[7];
    const float* w_e2  = (const float*)d_in[8];  const float* b_e2  = (const float*)d_in[9];
    const float* w_d1  = (const float*)d_in[10]; const float* b_d1  = (const float*)d_in[11];
    const float* w_d2  = (const float*)d_in[12]; const float* b_d2  = (const float*)d_in[13];
    const float* w_off = (const float*)d_in[14]; const float* b_off = (const float*)d_in[15];
    const float* w_dcn = (const float*)d_in[16]; const float* b_dcn = (const float*)d_in[17];
    const float* w_c1  = (const float*)d_in[18]; const float* b_c1  = (const float*)d_in[19];
    const float* w_c2  = (const float*)d_in[20]; const float* b_c2  = (const float*)d_in[21];

    float* out  = (float*)d_out;
    float* oL1  = out;                                  // [4,96,128,128]
    float* oEN  = out + (size_t)BN*NF*HWSZ;             // [4,96,32,32]
    float* oQ   = oEN + (size_t)BN*NF*32*32;            // [4,96,32,32]
    float* oDEC = oQ  + (size_t)BN*NF*32*32;            // [4,96,128,128]

    float *t1, *t2, *e1b, *d1b, *offb, *Sb;
    cudaGetSymbolAddress((void**)&t1,   g_t1);
    cudaGetSymbolAddress((void**)&t2,   g_t2);
    cudaGetSymbolAddress((void**)&e1b,  g_e1);
    cudaGetSymbolAddress((void**)&d1b,  g_d1);
    cudaGetSymbolAddress((void**)&offb, g_off);
    cudaGetSymbolAddress((void**)&Sb,   g_S);

    // t = lrelu(conv(concat(ref, inp), oc1)); t = lrelu(conv(t, oc3))  [fp32: feeds quantizer]
    conv3x3_s1<<<dim3(16, 12, BN), 256>>>(ref, NF, inp, NF, w_oc1, b_oc1, t1, NF, 1);
    conv3x3_s1<<<dim3(16, 12, BN), 256>>>(t1, NF, nullptr, 0, w_oc3, b_oc3, t2, NF, 1);
    // encoder: e1 (stride2 + lrelu), e2 (stride2) -> en, q=round(en)  [fp32]
    conv3x3_s2<8><<<dim3(16, 12, BN), 256>>>(t2, 128, w_e1, b_e1, e1b, nullptr, 1);
    conv3x3_s2<2><<<dim3(4,  48, BN), 256>>>(e1b, 64, w_e2, b_e2, oEN, oQ, 0);
    // decoder: two 2x transpose convs [fp32: dec is a direct output]
    deconv3x3_x2<2><<<dim3(4,  48, BN), 256>>>(oQ,  32, w_d1, b_d1, d1b, 1);
    deconv3x3_x2<8><<<dim3(16, 12, BN), 256>>>(d1b, 64, w_d2, b_d2, oDEC, 0);
    // offset head (216 ch)  [tf32 tensor core]
    conv3x3_tf32<<<dim3(128, 7, BN), 256>>>(oDEC, NF, nullptr, 0, w_off, b_off, offb, 2*GD*K2T, 0);
    // deformable conv = bilinear sampling + 1x1 GEMM over 864 "channels"
    dcn_sample<<<(BN*GD*K2T*HWSZ)/256, 256>>>(ref, offb, Sb);
    gemm1x1_tf32<<<dim3(HWSZ/128, 3, BN), 256>>>(Sb, w_dcn, b_dcn, oL1);
    // fusion tail: o = lrelu(conv(concat(L1, ref), c1)); o = lrelu(conv(o, c2)); L1 += o  [tf32]
    conv3x3_tf32<<<dim3(128, 3, BN), 256>>>(oL1, NF, ref, NF, w_c1, b_c1, t1, NF, 1);
    conv3x3_tf32<<<dim3(128, 3, BN), 256>>>(t1, NF, nullptr, 0, w_c2, b_c2, oL1, NF, 3);
}

// round 3
// speedup vs baseline: 1.1407x; 1.1407x over previous
#include <cuda_runtime.h>
#include <math.h>
#include <stdint.h>

#define NF 96
#define GD 12
#define K2T 9
#define BN 4
#define HH 128
#define WW 128
#define HWSZ (HH*WW)

typedef unsigned long long ull;

// ---------------- scratch (device globals; no runtime allocation) ------------
__device__ float g_t1[BN*NF*HWSZ];            // oc1 out, later c1 out
__device__ float g_t2[BN*NF*HWSZ];            // oc3 out
__device__ float g_e1[BN*NF*64*64];           // e1 out
__device__ float g_d1[BN*NF*64*64];           // d1 out
__device__ float g_off[BN*2*GD*K2T*HWSZ];     // offset conv out (216 ch)
__device__ float g_S[BN*NF*K2T*HWSZ];         // DCN sampled tensor (864 "ch")

// ---------------- packed f32x2 helpers ----------------------------------------
__device__ __forceinline__ ull pk2(float lo, float hi) {
    ull r; asm("mov.b64 %0,{%1,%2};" : "=l"(r) : "f"(lo), "f"(hi)); return r;
}
__device__ __forceinline__ void upk2(ull v, float& lo, float& hi) {
    asm("mov.b64 {%0,%1},%2;" : "=f"(lo), "=f"(hi) : "l"(v));
}
__device__ __forceinline__ ull fma2(ull a, ull b, ull c) {
    ull d; asm("fma.rn.f32x2 %0,%1,%2,%3;" : "=l"(d) : "l"(a), "l"(b), "l"(c)); return d;
}

// ---------------- packed 3x3 stride-1 conv, H=W=128 ---------------------------
// tile 64x16 output, 256 threads, thread: 4 adjacent px (2 f32x2 pairs) x 8 oc.
// flags: bit0 = LReLU, bit1 = add into out (out += v)
__global__ __launch_bounds__(256) void conv3x3_s1p(
    const float* __restrict__ inA, int cinA,
    const float* __restrict__ inB, int cinB,
    const float* __restrict__ w, const float* __restrict__ bias,
    float* __restrict__ out, int cout, int flags)
{
    const int tid = threadIdx.x;
    const int tx = tid & 15;      // x group of 4
    const int ty = tid >> 4;      // y row
    const int x0 = (blockIdx.x & 1) * 64;
    const int y0 = (blockIdx.x >> 1) * 16;
    const int ocb = blockIdx.y * 8;
    const int n = blockIdx.z;
    const int cin = cinA + cinB;

    __shared__ float sIn[4][18][68];     // rows 16B-aligned (68*4=272=16*17)
    __shared__ ull   sWp[8][4][9];       // prepacked {w,w}

    ull acc[8][2];
#pragma unroll
    for (int o = 0; o < 8; o++) { acc[o][0] = 0ull; acc[o][1] = 0ull; }

    for (int ic0 = 0; ic0 < cin; ic0 += 4) {
        __syncthreads();
        // stage 4 x 18 x 66 input halo (zero padded)
        for (int idx = tid; idx < 4*18*66; idx += 256) {
            int ic = idx / (18*66);
            int r  = (idx / 66) % 18;
            int c  = idx % 66;
            int gy = y0 - 1 + r;
            int gx = x0 - 1 + c;
            float v = 0.f;
            if ((unsigned)gy < (unsigned)HH && (unsigned)gx < (unsigned)WW) {
                int icg = ic0 + ic;
                const float* p = (icg < cinA)
                    ? (inA + ((size_t)(n*cinA + icg)*HH + gy)*WW + gx)
                    : (inB + ((size_t)(n*cinB + (icg - cinA))*HH + gy)*WW + gx);
                v = *p;
            }
            sIn[ic][r][c] = v;
        }
        // stage 8 oc x 4 ic x 9 weights, duplicated into both f32x2 lanes
        for (int idx = tid; idx < 8*4*9; idx += 256) {
            int o  = idx / 36;
            int ic = (idx / 9) % 4;
            int t  = idx % 9;
            float wv = w[((size_t)(ocb + o)*cin + ic0 + ic)*9 + t];
            sWp[o][ic][t] = pk2(wv, wv);
        }
        __syncthreads();

#pragma unroll
        for (int ic = 0; ic < 4; ic++) {
#pragma unroll
            for (int dy = 0; dy < 3; dy++) {
                const float* rp = &sIn[ic][ty + dy][4*tx];
                float4 va = *(const float4*)rp;            // v0..v3
                float2 vb = *(const float2*)(rp + 4);      // v4, v5
                ull q01 = pk2(va.x, va.y);
                ull q12 = pk2(va.y, va.z);
                ull q23 = pk2(va.z, va.w);
                ull q34 = pk2(va.w, vb.x);
                ull q45 = pk2(vb.x, vb.y);
#pragma unroll
                for (int o = 0; o < 8; o++) {
                    ull w0 = sWp[o][ic][dy*3 + 0];
                    acc[o][0] = fma2(w0, q01, acc[o][0]);
                    acc[o][1] = fma2(w0, q23, acc[o][1]);
                    ull w1 = sWp[o][ic][dy*3 + 1];
                    acc[o][0] = fma2(w1, q12, acc[o][0]);
                    acc[o][1] = fma2(w1, q34, acc[o][1]);
                    ull w2 = sWp[o][ic][dy*3 + 2];
                    acc[o][0] = fma2(w2, q23, acc[o][0]);
                    acc[o][1] = fma2(w2, q45, acc[o][1]);
                }
            }
        }
    }

    const int y = y0 + ty;
    const int xb = x0 + 4*tx;
#pragma unroll
    for (int o = 0; o < 8; o++) {
        float bv = bias[ocb + o];
        float v0, v1, v2, v3;
        upk2(acc[o][0], v0, v1);
        upk2(acc[o][1], v2, v3);
        v0 += bv; v1 += bv; v2 += bv; v3 += bv;
        if (flags & 1) {
            v0 = (v0 >= 0.f) ? v0 : 0.1f*v0;
            v1 = (v1 >= 0.f) ? v1 : 0.1f*v1;
            v2 = (v2 >= 0.f) ? v2 : 0.1f*v2;
            v3 = (v3 >= 0.f) ? v3 : 0.1f*v3;
        }
        float* op = out + ((size_t)(n*cout + ocb + o)*HH + y)*WW + xb;
        if (flags & 2) {
            float4 prev = *(float4*)op;
            prev.x += v0; prev.y += v1; prev.z += v2; prev.w += v3;
            *(float4*)op = prev;
        } else {
            float4 vv = make_float4(v0, v1, v2, v3);
            *(float4*)op = vv;
        }
    }
}

// ---------------- 3x3 stride-2 conv (SAME: pad_lo=0, pad_hi=1), packed oc -----
// cin = cout = 96. out tile 16x16, 8 oc (4 f32x2 pairs) per thread.
__global__ __launch_bounds__(256) void conv3x3_s2p(
    const float* __restrict__ in, int Hin,
    const float* __restrict__ w, const float* __restrict__ bias,
    float* __restrict__ out, float* __restrict__ out_q, int flags)
{
    const int tid = threadIdx.x;
    const int tx = tid & 15;
    const int ty = tid >> 4;
    const int Hout = Hin >> 1;
    const int tilesX = Hout >> 4;
    const int x0 = (blockIdx.x % tilesX) * 16;
    const int y0 = (blockIdx.x / tilesX) * 16;
    const int ocb = blockIdx.y * 8;
    const int n = blockIdx.z;

    __shared__ float sIn[2][33][34];
    __shared__ ull   sWp[4][2][9];   // {w[2p], w[2p+1]} pairs

    ull acc[4];
#pragma unroll
    for (int p = 0; p < 4; p++) acc[p] = 0ull;

    for (int ic0 = 0; ic0 < NF; ic0 += 2) {
        __syncthreads();
        for (int idx = tid; idx < 2*33*33; idx += 256) {
            int ic = idx / (33*33);
            int r  = (idx / 33) % 33;
            int c  = idx % 33;
            int gy = 2*y0 + r;
            int gx = 2*x0 + c;
            float v = 0.f;
            if (gy < Hin && gx < Hin) {
                v = in[((size_t)(n*NF + ic0 + ic)*Hin + gy)*Hin + gx];
            }
            sIn[ic][r][c] = v;
        }
        for (int idx = tid; idx < 4*2*9; idx += 256) {
            int p  = idx / 18;
            int ic = (idx / 9) % 2;
            int t  = idx % 9;
            float w0 = w[((size_t)(ocb + 2*p    )*NF + ic0 + ic)*9 + t];
            float w1 = w[((size_t)(ocb + 2*p + 1)*NF + ic0 + ic)*9 + t];
            sWp[p][ic][t] = pk2(w0, w1);
        }
        __syncthreads();

#pragma unroll
        for (int ic = 0; ic < 2; ic++) {
#pragma unroll
            for (int dy = 0; dy < 3; dy++) {
#pragma unroll
                for (int dx = 0; dx < 3; dx++) {
                    float xv = sIn[ic][2*ty + dy][2*tx + dx];
                    ull xq = pk2(xv, xv);
#pragma unroll
                    for (int p = 0; p < 4; p++)
                        acc[p] = fma2(sWp[p][ic][dy*3 + dx], xq, acc[p]);
                }
            }
        }
    }

#pragma unroll
    for (int p = 0; p < 4; p++) {
        float v0, v1;
        upk2(acc[p], v0, v1);
        v0 += bias[ocb + 2*p];
        v1 += bias[ocb + 2*p + 1];
        if (flags & 1) {
            v0 = (v0 >= 0.f) ? v0 : 0.1f*v0;
            v1 = (v1 >= 0.f) ? v1 : 0.1f*v1;
        }
        size_t oi0 = ((size_t)(n*NF + ocb + 2*p    )*Hout + (y0 + ty))*Hout + (x0 + tx);
        size_t oi1 = ((size_t)(n*NF + ocb + 2*p + 1)*Hout + (y0 + ty))*Hout + (x0 + tx);
        out[oi0] = v0;
        out[oi1] = v1;
        if (out_q) { out_q[oi0] = rintf(v0); out_q[oi1] = rintf(v1); }
    }
}

// ---------------- 3x3 stride-2 transpose conv (2x upsample), fp32 scalar ------
__global__ __launch_bounds__(256) void deconv3x3_x2(
    const float* __restrict__ in, int Hin,
    const float* __restrict__ w, const float* __restrict__ bias,
    float* __restrict__ out, int flags)
{
    const int tid = threadIdx.x;
    const int tx = tid & 15;
    const int ty = tid >> 4;
    const int Hout = Hin * 2;
    const int tilesX = Hout >> 5;
    const int tX = blockIdx.x % tilesX;
    const int tY = blockIdx.x / tilesX;
    const int xin0 = tX * 16, yin0 = tY * 16;
    const int x0o = tX * 32, y0o = tY * 32;
    const int ocb = blockIdx.y * 8;
    const int n = blockIdx.z;

    __shared__ float sIn[4][17][18];
    __shared__ float sW[8][4][9];

    float aEE[8], aEO[8], aOE[8], aOO[8];
#pragma unroll
    for (int o = 0; o < 8; o++) { aEE[o]=0.f; aEO[o]=0.f; aOE[o]=0.f; aOO[o]=0.f; }

    for (int ic0 = 0; ic0 < NF; ic0 += 4) {
        __syncthreads();
        for (int idx = tid; idx < 4*17*17; idx += 256) {
            int ic = idx / (17*17);
            int r  = (idx / 17) % 17;
            int c  = idx % 17;
            int gy = yin0 - 1 + r;
            int gx = xin0 - 1 + c;
            float v = 0.f;
            if ((unsigned)gy < (unsigned)Hin && (unsigned)gx < (unsigned)Hin) {
                v = in[((size_t)(n*NF + ic0 + ic)*Hin + gy)*Hin + gx];
            }
            sIn[ic][r][c] = v;
        }
        for (int idx = tid; idx < 8*4*9; idx += 256) {
            int o  = idx / 36;
            int ic = (idx / 9) % 4;
            int t  = idx % 9;
            sW[o][ic][t] = w[((size_t)(ocb + o)*NF + ic0 + ic)*9 + t];
        }
        __syncthreads();

#pragma unroll
        for (int ic = 0; ic < 4; ic++) {
            float v00 = sIn[ic][ty    ][tx    ];
            float v01 = sIn[ic][ty    ][tx + 1];
            float v10 = sIn[ic][ty + 1][tx    ];
            float v11 = sIn[ic][ty + 1][tx + 1];
#pragma unroll
            for (int o = 0; o < 8; o++) {
                const float* wp = &sW[o][ic][0];
                aEE[o] = fmaf(wp[0], v00, aEE[o]);
                aEE[o] = fmaf(wp[2], v01, aEE[o]);
                aEE[o] = fmaf(wp[6], v10, aEE[o]);
                aEE[o] = fmaf(wp[8], v11, aEE[o]);
                aEO[o] = fmaf(wp[1], v01, aEO[o]);
                aEO[o] = fmaf(wp[7], v11, aEO[o]);
                aOE[o] = fmaf(wp[3], v10, aOE[o]);
                aOE[o] = fmaf(wp[5], v11, aOE[o]);
                aOO[o] = fmaf(wp[4], v11, aOO[o]);
            }
        }
    }

    const int ye = y0o + 2*ty, xe = x0o + 2*tx;
#pragma unroll
    for (int o = 0; o < 8; o++) {
        float bv = bias[ocb + o];
        float vEE = aEE[o] + bv, vEO = aEO[o] + bv, vOE = aOE[o] + bv, vOO = aOO[o] + bv;
        if (flags & 1) {
            vEE = (vEE >= 0.f) ? vEE : 0.1f*vEE;
            vEO = (vEO >= 0.f) ? vEO : 0.1f*vEO;
            vOE = (vOE >= 0.f) ? vOE : 0.1f*vOE;
            vOO = (vOO >= 0.f) ? vOO : 0.1f*vOO;
        }
        size_t base = ((size_t)(n*NF + ocb + o)*Hout + ye)*Hout + xe;
        out[base]            = vEE;
        out[base + 1]        = vEO;
        out[base + Hout]     = vOE;
        out[base + Hout + 1] = vOO;
    }
}

// ---------------- DCNv1 bilinear sampling -------------------------------------
__global__ __launch_bounds__(256) void dcn_sample(
    const float* __restrict__ ref, const float* __restrict__ off,
    float* __restrict__ S)
{
    int idx = blockIdx.x * 256 + threadIdx.x;
    if (idx >= BN*GD*K2T*HWSZ) return;
    int p = idx & (HWSZ - 1);
    int t = idx >> 14;
    int k = t % 9;  t /= 9;
    int g = t % GD;
    int n = t / GD;
    int y = p >> 7, x = p & 127;

    int offc = (g*9 + k)*2;
    float dy = off[((size_t)(n*2*GD*K2T + offc    ))*HWSZ + p];
    float dx = off[((size_t)(n*2*GD*K2T + offc + 1))*HWSZ + p];
    float py = (float)y + (float)(k/3 - 1) + dy;
    float px = (float)x + (float)(k%3 - 1) + dx;
    float fy = floorf(py), fx = floorf(px);
    float wy = py - fy, wx = px - fx;
    int iy = (int)fy, ix = (int)fx;

    float wgt[4]; int ofs[4];
#pragma unroll
    for (int r = 0; r < 2; r++) {
#pragma unroll
        for (int c = 0; c < 2; c++) {
            int yy = iy + r, xx = ix + c;
            bool val = ((unsigned)yy < (unsigned)HH) && ((unsigned)xx < (unsigned)WW);
            float wv = (r ? wy : 1.f - wy) * (c ? wx : 1.f - wx);
            wgt[r*2 + c] = val ? wv : 0.f;
            ofs[r*2 + c] = val ? (yy*WW + xx) : 0;
        }
    }

    const float* base = ref + (size_t)(n*NF + g*8)*HWSZ;
    float* so = S + ((size_t)(n*NF + g*8)*9 + k)*HWSZ + p;
#pragma unroll
    for (int c = 0; c < 8; c++) {
        const float* bp = base + (size_t)c*HWSZ;
        float s = wgt[0]*bp[ofs[0]] + wgt[1]*bp[ofs[1]]
                + wgt[2]*bp[ofs[2]] + wgt[3]*bp[ofs[3]];
        so[(size_t)c*9*HWSZ] = s;
    }
}

// ---------------- packed 1x1 conv: out[96, HW] = W[96,864] * S[864, HW] -------
// tile: 256 px x 32 oc; thread: 4 adjacent px (2 pairs) x 8 oc.
__global__ __launch_bounds__(256) void conv1x1p(
    const float* __restrict__ S, const float* __restrict__ w,
    const float* __restrict__ bias, float* __restrict__ out)
{
    const int tid = threadIdx.x;
    const int px0 = (tid & 63) * 4;    // 4 adjacent pixels
    const int to  = tid >> 6;          // 0..3 -> oc sub-block
    const int p0  = blockIdx.x * 256;
    const int ocb = blockIdx.y * 32;
    const int n   = blockIdx.z;
    const int CIN = NF * K2T;          // 864

    __shared__ float sS[8][256];
    __shared__ ull   sWp[32][8];       // {w,w}

    ull acc[8][2];
#pragma unroll
    for (int o = 0; o < 8; o++) { acc[o][0] = 0ull; acc[o][1] = 0ull; }

    for (int ic0 = 0; ic0 < CIN; ic0 += 8) {
        __syncthreads();
        {
            int k = tid >> 5;
            int rem = (tid & 31) * 8;
            const float* sp = S + ((size_t)(n*CIN + ic0 + k))*HWSZ + p0 + rem;
            float4 a = *(const float4*)sp;
            float4 b = *(const float4*)(sp + 4);
            *(float4*)&sS[k][rem]     = a;
            *(float4*)&sS[k][rem + 4] = b;
            int o = tid >> 3, kk = tid & 7;
            float wv = w[(size_t)(ocb + o)*CIN + ic0 + kk];
            sWp[o][kk] = pk2(wv, wv);
        }
        __syncthreads();

#pragma unroll
        for (int k = 0; k < 8; k++) {
            float4 xv = *(const float4*)&sS[k][px0];
            ull q01 = pk2(xv.x, xv.y);
            ull q23 = pk2(xv.z, xv.w);
#pragma unroll
            for (int o = 0; o < 8; o++) {
                ull wq = sWp[to*8 + o][k];
                acc[o][0] = fma2(wq, q01, acc[o][0]);
                acc[o][1] = fma2(wq, q23, acc[o][1]);
            }
        }
    }

#pragma unroll
    for (int o = 0; o < 8; o++) {
        float bv = bias[ocb + to*8 + o];
        float v0, v1, v2, v3;
        upk2(acc[o][0], v0, v1);
        upk2(acc[o][1], v2, v3);
        float4 vv = make_float4(v0 + bv, v1 + bv, v2 + bv, v3 + bv);
        *(float4*)(out + ((size_t)(n*NF + ocb + to*8 + o))*HWSZ + p0 + px0) = vv;
    }
}

// ------------------------------ launch ---------------------------------------
extern "C" void kernel_launch(void* const* d_in, const int* in_sizes, int n_in,
                              void* d_out, int out_size)
{
    const float* ref   = (const float*)d_in[0];
    const float* inp   = (const float*)d_in[1];
    const float* w_oc1 = (const float*)d_in[2];  const float* b_oc1 = (const float*)d_in[3];
    const float* w_oc3 = (const float*)d_in[4];  const float* b_oc3 = (const float*)d_in[5];
    const float* w_e1  = (const float*)d_in[6];  const float* b_e1  = (const float*)d_in[7];
    const float* w_e2  = (const float*)d_in[8];  const float* b_e2  = (const float*)d_in[9];
    const float* w_d1  = (const float*)d_in[10]; const float* b_d1  = (const float*)d_in[11];
    const float* w_d2  = (const float*)d_in[12]; const float* b_d2  = (const float*)d_in[13];
    const float* w_off = (const float*)d_in[14]; const float* b_off = (const float*)d_in[15];
    const float* w_dcn = (const float*)d_in[16]; const float* b_dcn = (const float*)d_in[17];
    const float* w_c1  = (const float*)d_in[18]; const float* b_c1  = (const float*)d_in[19];
    const float* w_c2  = (const float*)d_in[20]; const float* b_c2  = (const float*)d_in[21];

    float* out  = (float*)d_out;
    float* oL1  = out;                                  // [4,96,128,128]
    float* oEN  = out + (size_t)BN*NF*HWSZ;             // [4,96,32,32]
    float* oQ   = oEN + (size_t)BN*NF*32*32;            // [4,96,32,32]
    float* oDEC = oQ  + (size_t)BN*NF*32*32;            // [4,96,128,128]

    float *t1, *t2, *e1b, *d1b, *offb, *Sb;
    cudaGetSymbolAddress((void**)&t1,   g_t1);
    cudaGetSymbolAddress((void**)&t2,   g_t2);
    cudaGetSymbolAddress((void**)&e1b,  g_e1);
    cudaGetSymbolAddress((void**)&d1b,  g_d1);
    cudaGetSymbolAddress((void**)&offb, g_off);
    cudaGetSymbolAddress((void**)&Sb,   g_S);

    // t = lrelu(conv(concat(ref, inp), oc1)); t = lrelu(conv(t, oc3))
    conv3x3_s1p<<<dim3(16, 12, BN), 256>>>(ref, NF, inp, NF, w_oc1, b_oc1, t1, NF, 1);
    conv3x3_s1p<<<dim3(16, 12, BN), 256>>>(t1, NF, nullptr, 0, w_oc3, b_oc3, t2, NF, 1);
    // encoder: e1 (stride2 + lrelu), e2 (stride2) -> en, q=round(en)
    conv3x3_s2p<<<dim3(16, 12, BN), 256>>>(t2, 128, w_e1, b_e1, e1b, nullptr, 1);
    conv3x3_s2p<<<dim3(4,  12, BN), 256>>>(e1b, 64, w_e2, b_e2, oEN, oQ, 0);
    // decoder: two 2x transpose convs
    deconv3x3_x2<<<dim3(4,  12, BN), 256>>>(oQ,  32, w_d1, b_d1, d1b, 1);
    deconv3x3_x2<<<dim3(16, 12, BN), 256>>>(d1b, 64, w_d2, b_d2, oDEC, 0);
    // offset head (216 ch)
    conv3x3_s1p<<<dim3(16, 27, BN), 256>>>(oDEC, NF, nullptr, 0, w_off, b_off, offb, 2*GD*K2T, 0);
    // deformable conv = bilinear sampling + 1x1 GEMM over 864 "channels"
    dcn_sample<<<(BN*GD*K2T*HWSZ)/256, 256>>>(ref, offb, Sb);
    conv1x1p<<<dim3(HWSZ/256, 3, BN), 256>>>(Sb, w_dcn, b_dcn, oL1);
    // fusion tail: o = lrelu(conv(concat(L1, ref), c1)); o = lrelu(conv(o, c2)); L1 += o
    conv3x3_s1p<<<dim3(16, 12, BN), 256>>>(oL1, NF, ref, NF, w_c1, b_c1, t1, NF, 1);
    conv3x3_s1p<<<dim3(16, 12, BN), 256>>>(t1, NF, nullptr, 0, w_c2, b_c2, oL1, NF, 3);
}

// round 4
// speedup vs baseline: 1.7543x; 1.5380x over previous
#include <cuda_runtime.h>
#include <math.h>
#include <stdint.h>

#define NF 96
#define GD 12
#define K2T 9
#define BN 4
#define HH 128
#define WW 128
#define HWSZ (HH*WW)

// ---------------- scratch (device globals; no runtime allocation) ------------
__device__ float g_t1[BN*NF*HWSZ];            // oc1 out, later c1 out
__device__ float g_t2[BN*NF*HWSZ];            // oc3 out
__device__ float g_e1[BN*NF*64*64];           // e1 out
__device__ float g_d1[BN*NF*64*64];           // d1 out
__device__ float g_off[BN*2*GD*K2T*HWSZ];     // offset conv out (216 ch)
__device__ float g_S[BN*NF*K2T*HWSZ];         // DCN sampled tensor (864 "ch")

// ============ pipelined 3x3 stride-1 conv, H=W=128 ============================
// tile 64x16 output, 256 threads, thread: 4 adjacent px x 8 oc.
// double-buffered smem, register prefetch, ONE sync per ic-chunk (4 ic).
// flags: bit0 = LReLU, bit1 = add into out (out += v)
__global__ __launch_bounds__(256) void conv3x3_s1v2(
    const float* __restrict__ inA, int cinA,
    const float* __restrict__ inB, int cinB,
    const float* __restrict__ w, const float* __restrict__ bias,
    float* __restrict__ out, int cout, int flags)
{
    const int tid = threadIdx.x;
    const int tx = tid & 15;
    const int ty = tid >> 4;
    const int x0 = (blockIdx.x & 1) * 64;
    const int y0 = (blockIdx.x >> 1) * 16;
    const int ocb = blockIdx.y * 8;
    const int n = blockIdx.z;
    const int cin = cinA + cinB;
    const int nch = cin >> 2;

    __shared__ float sIn[2][4][18][68];   // rows 16B-aligned
    __shared__ float sW[2][8*4*9];

    float rI[19];
    float rw0, rw1;

// prefetch one ic-chunk (4 ic) of the 4x18x66 halo + 288 weights into registers
#define S1_LOAD(IC0)                                                           \
    {                                                                          \
        const int ic0_ = (IC0);                                                \
        _Pragma("unroll")                                                      \
        for (int k = 0; k < 19; k++) {                                         \
            int idx = tid + 256*k;                                             \
            if (k < 18 || tid < 144) {                                         \
                int ic  = idx / 1188;                                          \
                int rem = idx - ic*1188;                                       \
                int rr  = rem / 66;                                            \
                int cc  = rem - rr*66;                                         \
                int gy = y0 - 1 + rr;                                          \
                int gx = x0 - 1 + cc;                                          \
                bool inb = ((unsigned)gy < (unsigned)HH) &&                    \
                           ((unsigned)gx < (unsigned)WW);                      \
                int icg = ic0_ + ic;                                           \
                const float* p = (icg < cinA)                                  \
                    ? (inA + ((size_t)(n*cinA + icg)*HH + gy)*WW + gx)         \
                    : (inB + ((size_t)(n*cinB + (icg - cinA))*HH + gy)*WW + gx);\
                rI[k] = inb ? __ldg(p) : 0.f;                                  \
            }                                                                  \
        }                                                                      \
        {                                                                      \
            int o  = tid / 36;                                                 \
            int ic = (tid / 9) % 4;                                            \
            int t  = tid % 9;                                                  \
            rw0 = w[((size_t)(ocb + o)*cin + ic0_ + ic)*9 + t];                \
            if (tid < 32) {                                                    \
                int idx = tid + 256;                                           \
                int o2  = idx / 36;                                            \
                int ic2 = (idx / 9) % 4;                                       \
                int t2  = idx % 9;                                             \
                rw1 = w[((size_t)(ocb + o2)*cin + ic0_ + ic2)*9 + t2];         \
            }                                                                  \
        }                                                                      \
    }

#define S1_STORE(B)                                                            \
    {                                                                          \
        float* sb = &sIn[B][0][0][0];                                          \
        _Pragma("unroll")                                                      \
        for (int k = 0; k < 19; k++) {                                         \
            int idx = tid + 256*k;                                             \
            if (k < 18 || tid < 144) {                                         \
                int ic  = idx / 1188;                                          \
                int rem = idx - ic*1188;                                       \
                int rr  = rem / 66;                                            \
                int cc  = rem - rr*66;                                         \
                sb[(ic*18 + rr)*68 + cc] = rI[k];                              \
            }                                                                  \
        }                                                                      \
        sW[B][tid] = rw0;                                                      \
        if (tid < 32) sW[B][tid + 256] = rw1;                                  \
    }

    float acc[8][4];
#pragma unroll
    for (int o = 0; o < 8; o++)
#pragma unroll
        for (int j = 0; j < 4; j++) acc[o][j] = 0.f;

    S1_LOAD(0);
    S1_STORE(0);
    __syncthreads();

    for (int c = 0; c < nch; c++) {
        const int b = c & 1;
        if (c + 1 < nch) S1_LOAD((c + 1)*4);

#pragma unroll
        for (int ic = 0; ic < 4; ic++) {
#pragma unroll
            for (int dy = 0; dy < 3; dy++) {
                const float* rp = &sIn[b][ic][ty + dy][4*tx];
                float4 va = *(const float4*)rp;
                float2 vb = *(const float2*)(rp + 4);
                float v[6] = {va.x, va.y, va.z, va.w, vb.x, vb.y};
                const float* wrow = &sW[b][(0*4 + ic)*9 + dy*3];
#pragma unroll
                for (int dx = 0; dx < 3; dx++) {
                    float wv[8];
#pragma unroll
                    for (int o = 0; o < 8; o++) wv[o] = wrow[o*36 + dx];
#pragma unroll
                    for (int j = 0; j < 4; j++) {
                        float xv = v[j + dx];
#pragma unroll
                        for (int o = 0; o < 8; o++)
                            acc[o][j] = fmaf(wv[o], xv, acc[o][j]);
                    }
                }
            }
        }

        if (c + 1 < nch) {
            S1_STORE((c + 1) & 1);
            __syncthreads();
        }
    }

    const int y = y0 + ty;
    const int xb = x0 + 4*tx;
#pragma unroll
    for (int o = 0; o < 8; o++) {
        float bv = bias[ocb + o];
        float v0 = acc[o][0] + bv, v1 = acc[o][1] + bv;
        float v2 = acc[o][2] + bv, v3 = acc[o][3] + bv;
        if (flags & 1) {
            v0 = (v0 >= 0.f) ? v0 : 0.1f*v0;
            v1 = (v1 >= 0.f) ? v1 : 0.1f*v1;
            v2 = (v2 >= 0.f) ? v2 : 0.1f*v2;
            v3 = (v3 >= 0.f) ? v3 : 0.1f*v3;
        }
        float* op = out + ((size_t)(n*cout + ocb + o)*HH + y)*WW + xb;
        if (flags & 2) {
            float4 prev = *(float4*)op;
            prev.x += v0; prev.y += v1; prev.z += v2; prev.w += v3;
            *(float4*)op = prev;
        } else {
            *(float4*)op = make_float4(v0, v1, v2, v3);
        }
    }
#undef S1_LOAD
#undef S1_STORE
}

// ============ pipelined 3x3 stride-2 conv (SAME: pad_lo=0, pad_hi=1) =========
// cin=cout=96. out tile 16x16, 8 oc/thread; 2-ic chunks, double buffered.
__global__ __launch_bounds__(256) void conv3x3_s2v2(
    const float* __restrict__ in, int Hin,
    const float* __restrict__ w, const float* __restrict__ bias,
    float* __restrict__ out, float* __restrict__ out_q, int flags)
{
    const int tid = threadIdx.x;
    const int tx = tid & 15;
    const int ty = tid >> 4;
    const int Hout = Hin >> 1;
    const int tilesX = Hout >> 4;
    const int x0 = (blockIdx.x % tilesX) * 16;
    const int y0 = (blockIdx.x / tilesX) * 16;
    const int ocb = blockIdx.y * 8;
    const int n = blockIdx.z;

    __shared__ float sIn[2][2][33][34];
    __shared__ float sW[2][8*2*9];

    float rI[9];
    float rw0;

#define S2_LOAD(IC0)                                                           \
    {                                                                          \
        const int ic0_ = (IC0);                                                \
        _Pragma("unroll")                                                      \
        for (int k = 0; k < 9; k++) {                                          \
            int idx = tid + 256*k;                                             \
            if (k < 8 || tid < 130) {                                          \
                int ic  = idx / 1089;                                          \
                int rem = idx - ic*1089;                                       \
                int rr  = rem / 33;                                            \
                int cc  = rem - rr*33;                                         \
                int gy = 2*y0 + rr;                                            \
                int gx = 2*x0 + cc;                                            \
                bool inb = (gy < Hin) && (gx < Hin);                           \
                rI[k] = inb ? __ldg(in + ((size_t)(n*NF + ic0_ + ic)*Hin + gy)*Hin + gx) : 0.f; \
            }                                                                  \
        }                                                                      \
        if (tid < 144) {                                                       \
            int o  = tid / 18;                                                 \
            int ic = (tid / 9) % 2;                                            \
            int t  = tid % 9;                                                  \
            rw0 = w[((size_t)(ocb + o)*NF + ic0_ + ic)*9 + t];                 \
        }                                                                      \
    }

#define S2_STORE(B)                                                            \
    {                                                                          \
        float* sb = &sIn[B][0][0][0];                                          \
        _Pragma("unroll")                                                      \
        for (int k = 0; k < 9; k++) {                                          \
            int idx = tid + 256*k;                                             \
            if (k < 8 || tid < 130) {                                          \
                int ic  = idx / 1089;                                          \
                int rem = idx - ic*1089;                                       \
                int rr  = rem / 33;                                            \
                int cc  = rem - rr*33;                                         \
                sb[(ic*33 + rr)*34 + cc] = rI[k];                              \
            }                                                                  \
        }                                                                      \
        if (tid < 144) sW[B][tid] = rw0;                                       \
    }

    float acc[8];
#pragma unroll
    for (int o = 0; o < 8; o++) acc[o] = 0.f;

    S2_LOAD(0);
    S2_STORE(0);
    __syncthreads();

    const int nch = NF/2;
    for (int c = 0; c < nch; c++) {
        const int b = c & 1;
        if (c + 1 < nch) S2_LOAD((c + 1)*2);

#pragma unroll
        for (int ic = 0; ic < 2; ic++) {
#pragma unroll
            for (int dy = 0; dy < 3; dy++) {
#pragma unroll
                for (int dx = 0; dx < 3; dx++) {
                    float xv = sIn[b][ic][2*ty + dy][2*tx + dx];
                    const float* wp = &sW[b][ic*9 + dy*3 + dx];
#pragma unroll
                    for (int o = 0; o < 8; o++)
                        acc[o] = fmaf(wp[o*18], xv, acc[o]);
                }
            }
        }

        if (c + 1 < nch) {
            S2_STORE((c + 1) & 1);
            __syncthreads();
        }
    }

#pragma unroll
    for (int o = 0; o < 8; o++) {
        float v = acc[o] + bias[ocb + o];
        if (flags & 1) v = (v >= 0.f) ? v : 0.1f * v;
        size_t oi = ((size_t)(n*NF + ocb + o)*Hout + (y0 + ty))*Hout + (x0 + tx);
        out[oi] = v;
        if (out_q) out_q[oi] = rintf(v);   // round half to even == jnp.round
    }
#undef S2_LOAD
#undef S2_STORE
}

// ============ 3x3 stride-2 transpose conv (2x upsample), round-1 proven ======
__global__ __launch_bounds__(256) void deconv3x3_x2(
    const float* __restrict__ in, int Hin,
    const float* __restrict__ w, const float* __restrict__ bias,
    float* __restrict__ out, int flags)
{
    const int tid = threadIdx.x;
    const int tx = tid & 15;
    const int ty = tid >> 4;
    const int Hout = Hin * 2;
    const int tilesX = Hout >> 5;
    const int tX = blockIdx.x % tilesX;
    const int tY = blockIdx.x / tilesX;
    const int xin0 = tX * 16, yin0 = tY * 16;
    const int x0o = tX * 32, y0o = tY * 32;
    const int ocb = blockIdx.y * 8;
    const int n = blockIdx.z;

    __shared__ float sIn[4][17][18];
    __shared__ float sW[8][4][9];

    float aEE[8], aEO[8], aOE[8], aOO[8];
#pragma unroll
    for (int o = 0; o < 8; o++) { aEE[o]=0.f; aEO[o]=0.f; aOE[o]=0.f; aOO[o]=0.f; }

    for (int ic0 = 0; ic0 < NF; ic0 += 4) {
        __syncthreads();
        for (int idx = tid; idx < 4*17*17; idx += 256) {
            int ic = idx / (17*17);
            int r  = (idx / 17) % 17;
            int c  = idx % 17;
            int gy = yin0 - 1 + r;
            int gx = xin0 - 1 + c;
            float v = 0.f;
            if ((unsigned)gy < (unsigned)Hin && (unsigned)gx < (unsigned)Hin) {
                v = in[((size_t)(n*NF + ic0 + ic)*Hin + gy)*Hin + gx];
            }
            sIn[ic][r][c] = v;
        }
        for (int idx = tid; idx < 8*4*9; idx += 256) {
            int o  = idx / 36;
            int ic = (idx / 9) % 4;
            int t  = idx % 9;
            sW[o][ic][t] = w[((size_t)(ocb + o)*NF + ic0 + ic)*9 + t];
        }
        __syncthreads();

#pragma unroll
        for (int ic = 0; ic < 4; ic++) {
            float v00 = sIn[ic][ty    ][tx    ];
            float v01 = sIn[ic][ty    ][tx + 1];
            float v10 = sIn[ic][ty + 1][tx    ];
            float v11 = sIn[ic][ty + 1][tx + 1];
#pragma unroll
            for (int o = 0; o < 8; o++) {
                const float* wp = &sW[o][ic][0];
                aEE[o] = fmaf(wp[0], v00, aEE[o]);
                aEE[o] = fmaf(wp[2], v01, aEE[o]);
                aEE[o] = fmaf(wp[6], v10, aEE[o]);
                aEE[o] = fmaf(wp[8], v11, aEE[o]);
                aEO[o] = fmaf(wp[1], v01, aEO[o]);
                aEO[o] = fmaf(wp[7], v11, aEO[o]);
                aOE[o] = fmaf(wp[3], v10, aOE[o]);
                aOE[o] = fmaf(wp[5], v11, aOE[o]);
                aOO[o] = fmaf(wp[4], v11, aOO[o]);
            }
        }
    }

    const int ye = y0o + 2*ty, xe = x0o + 2*tx;
#pragma unroll
    for (int o = 0; o < 8; o++) {
        float bv = bias[ocb + o];
        float vEE = aEE[o] + bv, vEO = aEO[o] + bv, vOE = aOE[o] + bv, vOO = aOO[o] + bv;
        if (flags & 1) {
            vEE = (vEE >= 0.f) ? vEE : 0.1f*vEE;
            vEO = (vEO >= 0.f) ? vEO : 0.1f*vEO;
            vOE = (vOE >= 0.f) ? vOE : 0.1f*vOE;
            vOO = (vOO >= 0.f) ? vOO : 0.1f*vOO;
        }
        size_t base = ((size_t)(n*NF + ocb + o)*Hout + ye)*Hout + xe;
        out[base]            = vEE;
        out[base + 1]        = vEO;
        out[base + Hout]     = vOE;
        out[base + Hout + 1] = vOO;
    }
}

// ============ DCNv1 bilinear sampling ========================================
__global__ __launch_bounds__(256) void dcn_sample(
    const float* __restrict__ ref, const float* __restrict__ off,
    float* __restrict__ S)
{
    int idx = blockIdx.x * 256 + threadIdx.x;
    if (idx >= BN*GD*K2T*HWSZ) return;
    int p = idx & (HWSZ - 1);
    int t = idx >> 14;
    int k = t % 9;  t /= 9;
    int g = t % GD;
    int n = t / GD;
    int y = p >> 7, x = p & 127;

    int offc = (g*9 + k)*2;
    float dy = off[((size_t)(n*2*GD*K2T + offc    ))*HWSZ + p];
    float dx = off[((size_t)(n*2*GD*K2T + offc + 1))*HWSZ + p];
    float py = (float)y + (float)(k/3 - 1) + dy;
    float px = (float)x + (float)(k%3 - 1) + dx;
    float fy = floorf(py), fx = floorf(px);
    float wy = py - fy, wx = px - fx;
    int iy = (int)fy, ix = (int)fx;

    float wgt[4]; int ofs[4];
#pragma unroll
    for (int r = 0; r < 2; r++) {
#pragma unroll
        for (int c = 0; c < 2; c++) {
            int yy = iy + r, xx = ix + c;
            bool val = ((unsigned)yy < (unsigned)HH) && ((unsigned)xx < (unsigned)WW);
            float wv = (r ? wy : 1.f - wy) * (c ? wx : 1.f - wx);
            wgt[r*2 + c] = val ? wv : 0.f;
            ofs[r*2 + c] = val ? (yy*WW + xx) : 0;
        }
    }

    const float* base = ref + (size_t)(n*NF + g*8)*HWSZ;
    float* so = S + ((size_t)(n*NF + g*8)*9 + k)*HWSZ + p;
#pragma unroll
    for (int c = 0; c < 8; c++) {
        const float* bp = base + (size_t)c*HWSZ;
        float s = wgt[0]*bp[ofs[0]] + wgt[1]*bp[ofs[1]]
                + wgt[2]*bp[ofs[2]] + wgt[3]*bp[ofs[3]];
        so[(size_t)c*9*HWSZ] = s;
    }
}

// ============ pipelined 1x1 conv: out[96,HW] = W[96,864] * S[864,HW] =========
// tile: 256 px x 32 oc; thread: 4 px (stride 64) x 8 oc; double buffered.
__global__ __launch_bounds__(256) void conv1x1v2(
    const float* __restrict__ S, const float* __restrict__ w,
    const float* __restrict__ bias, float* __restrict__ out)
{
    const int tid = threadIdx.x;
    const int tpx = tid & 63;
    const int to  = tid >> 6;
    const int p0  = blockIdx.x * 256;
    const int ocb = blockIdx.y * 32;
    const int n   = blockIdx.z;
    const int CIN = NF * K2T;          // 864

    __shared__ float sS[2][8][256];
    __shared__ float sW[2][32*8];

    float rD[8];
    float rw;

#define G1_LOAD(K0)                                                            \
    {                                                                          \
        const int k0_ = (K0);                                                  \
        _Pragma("unroll")                                                      \
        for (int ic = 0; ic < 8; ic++)                                         \
            rD[ic] = __ldg(S + ((size_t)(n*CIN + k0_ + ic))*HWSZ + p0 + tid);  \
        {                                                                      \
            int o = tid >> 3, kk = tid & 7;                                    \
            rw = w[(size_t)(ocb + o)*CIN + k0_ + kk];                          \
        }                                                                      \
    }

#define G1_STORE(B)                                                            \
    {                                                                          \
        _Pragma("unroll")                                                      \
        for (int ic = 0; ic < 8; ic++) sS[B][ic][tid] = rD[ic];                \
        sW[B][tid] = rw;                                                       \
    }

    float acc[8][4];
#pragma unroll
    for (int o = 0; o < 8; o++)
#pragma unroll
        for (int j = 0; j < 4; j++) acc[o][j] = 0.f;

    G1_LOAD(0);
    G1_STORE(0);
    __syncthreads();

    const int nch = CIN/8;
    for (int c = 0; c < nch; c++) {
        const int b = c & 1;
        if (c + 1 < nch) G1_LOAD((c + 1)*8);

#pragma unroll
        for (int k = 0; k < 8; k++) {
            float xv[4];
#pragma unroll
            for (int j = 0; j < 4; j++) xv[j] = sS[b][k][tpx + 64*j];
            float wv[8];
#pragma unroll
            for (int o = 0; o < 8; o++) wv[o] = sW[b][(to*8 + o)*8 + k];
#pragma unroll
            for (int o = 0; o < 8; o++)
#pragma unroll
                for (int j = 0; j < 4; j++)
                    acc[o][j] = fmaf(wv[o], xv[j], acc[o][j]);
        }

        if (c + 1 < nch) {
            G1_STORE((c + 1) & 1);
            __syncthreads();
        }
    }

#pragma unroll
    for (int o = 0; o < 8; o++) {
        float bv = bias[ocb + to*8 + o];
#pragma unroll
        for (int j = 0; j < 4; j++) {
            out[((size_t)(n*NF + ocb + to*8 + o))*HWSZ + p0 + tpx + 64*j] = acc[o][j] + bv;
        }
    }
#undef G1_LOAD
#undef G1_STORE
}

// ------------------------------ launch ---------------------------------------
extern "C" void kernel_launch(void* const* d_in, const int* in_sizes, int n_in,
                              void* d_out, int out_size)
{
    const float* ref   = (const float*)d_in[0];
    const float* inp   = (const float*)d_in[1];
    const float* w_oc1 = (const float*)d_in[2];  const float* b_oc1 = (const float*)d_in[3];
    const float* w_oc3 = (const float*)d_in[4];  const float* b_oc3 = (const float*)d_in[5];
    const float* w_e1  = (const float*)d_in[6];  const float* b_e1  = (const float*)d_in[7];
    const float* w_e2  = (const float*)d_in[8];  const float* b_e2  = (const float*)d_in[9];
    const float* w_d1  = (const float*)d_in[10]; const float* b_d1  = (const float*)d_in[11];
    const float* w_d2  = (const float*)d_in[12]; const float* b_d2  = (const float*)d_in[13];
    const float* w_off = (const float*)d_in[14]; const float* b_off = (const float*)d_in[15];
    const float* w_dcn = (const float*)d_in[16]; const float* b_dcn = (const float*)d_in[17];
    const float* w_c1  = (const float*)d_in[18]; const float* b_c1  = (const float*)d_in[19];
    const float* w_c2  = (const float*)d_in[20]; const float* b_c2  = (const float*)d_in[21];

    float* out  = (float*)d_out;
    float* oL1  = out;                                  // [4,96,128,128]
    float* oEN  = out + (size_t)BN*NF*HWSZ;             // [4,96,32,32]
    float* oQ   = oEN + (size_t)BN*NF*32*32;            // [4,96,32,32]
    float* oDEC = oQ  + (size_t)BN*NF*32*32;            // [4,96,128,128]

    float *t1, *t2, *e1b, *d1b, *offb, *Sb;
    cudaGetSymbolAddress((void**)&t1,   g_t1);
    cudaGetSymbolAddress((void**)&t2,   g_t2);
    cudaGetSymbolAddress((void**)&e1b,  g_e1);
    cudaGetSymbolAddress((void**)&d1b,  g_d1);
    cudaGetSymbolAddress((void**)&offb, g_off);
    cudaGetSymbolAddress((void**)&Sb,   g_S);

    // t = lrelu(conv(concat(ref, inp), oc1)); t = lrelu(conv(t, oc3))
    conv3x3_s1v2<<<dim3(16, 12, BN), 256>>>(ref, NF, inp, NF, w_oc1, b_oc1, t1, NF, 1);
    conv3x3_s1v2<<<dim3(16, 12, BN), 256>>>(t1, NF, nullptr, 0, w_oc3, b_oc3, t2, NF, 1);
    // encoder: e1 (stride2 + lrelu), e2 (stride2) -> en, q=round(en)
    conv3x3_s2v2<<<dim3(16, 12, BN), 256>>>(t2, 128, w_e1, b_e1, e1b, nullptr, 1);
    conv3x3_s2v2<<<dim3(4,  12, BN), 256>>>(e1b, 64, w_e2, b_e2, oEN, oQ, 0);
    // decoder: two 2x transpose convs
    deconv3x3_x2<<<dim3(4,  12, BN), 256>>>(oQ,  32, w_d1, b_d1, d1b, 1);
    deconv3x3_x2<<<dim3(16, 12, BN), 256>>>(d1b, 64, w_d2, b_d2, oDEC, 0);
    // offset head (216 ch)
    conv3x3_s1v2<<<dim3(16, 27, BN), 256>>>(oDEC, NF, nullptr, 0, w_off, b_off, offb, 2*GD*K2T, 0);
    // deformable conv = bilinear sampling + 1x1 GEMM over 864 "channels"
    dcn_sample<<<(BN*GD*K2T*HWSZ)/256, 256>>>(ref, offb, Sb);
    conv1x1v2<<<dim3(HWSZ/256, 3, BN), 256>>>(Sb, w_dcn, b_dcn, oL1);
    // fusion tail: o = lrelu(conv(concat(L1, ref), c1)); o = lrelu(conv(o, c2)); L1 += o
    conv3x3_s1v2<<<dim3(16, 12, BN), 256>>>(oL1, NF, ref, NF, w_c1, b_c1, t1, NF, 1);
    conv3x3_s1v2<<<dim3(16, 12, BN), 256>>>(t1, NF, nullptr, 0, w_c2, b_c2, oL1, NF, 3);
}

// round 5
// speedup vs baseline: 1.7561x; 1.0010x over previous
#include <cuda_runtime.h>
#include <math.h>
#include <stdint.h>

#define NF 96
#define GD 12
#define K2T 9
#define BN 4
#define HH 128
#define WW 128
#define HWSZ (HH*WW)

// ---------------- scratch (device globals; no runtime allocation) ------------
__device__ float g_t1[BN*NF*HWSZ];            // oc1 out, later c1 out
__device__ float g_t2[BN*NF*HWSZ];            // oc3 out
__device__ float g_e1[BN*NF*64*64];           // e1 out
__device__ float g_d1[BN*NF*64*64];           // d1 out
__device__ float g_off[BN*2*GD*K2T*HWSZ];     // offset conv out (216 ch)
__device__ float g_S[BN*NF*K2T*HWSZ];         // DCN sampled tensor (864 "ch")

// ============ pipelined 3x3 stride-1 conv, H=W=128 ============================
// tile 64x16 output, 256 threads, thread: 4 adjacent px x 8 oc.
// double-buffered smem, register prefetch, ONE sync per ic-chunk (4 ic).
// flags: bit0 = LReLU, bit1 = add into out (out += v)
__global__ __launch_bounds__(256) void conv3x3_s1v2(
    const float* __restrict__ inA, int cinA,
    const float* __restrict__ inB, int cinB,
    const float* __restrict__ w, const float* __restrict__ bias,
    float* __restrict__ out, int cout, int flags)
{
    const int tid = threadIdx.x;
    const int tx = tid & 15;
    const int ty = tid >> 4;
    const int x0 = (blockIdx.x & 1) * 64;
    const int y0 = (blockIdx.x >> 1) * 16;
    const int ocb = blockIdx.y * 8;
    const int n = blockIdx.z;
    const int cin = cinA + cinB;
    const int nch = cin >> 2;

    __shared__ float sIn[2][4][18][68];   // rows 16B-aligned
    __shared__ float sW[2][8*4*9];

    float rI[19];
    float rw0, rw1;

// prefetch one ic-chunk (4 ic) of the 4x18x66 halo + 288 weights into registers
#define S1_LOAD(IC0)                                                           \
    {                                                                          \
        const int ic0_ = (IC0);                                                \
        _Pragma("unroll")                                                      \
        for (int k = 0; k < 19; k++) {                                         \
            int idx = tid + 256*k;                                             \
            if (k < 18 || tid < 144) {                                         \
                int ic  = idx / 1188;                                          \
                int rem = idx - ic*1188;                                       \
                int rr  = rem / 66;                                            \
                int cc  = rem - rr*66;                                         \
                int gy = y0 - 1 + rr;                                          \
                int gx = x0 - 1 + cc;                                          \
                bool inb = ((unsigned)gy < (unsigned)HH) &&                    \
                           ((unsigned)gx < (unsigned)WW);                      \
                int icg = ic0_ + ic;                                           \
                const float* p = (icg < cinA)                                  \
                    ? (inA + ((size_t)(n*cinA + icg)*HH + gy)*WW + gx)         \
                    : (inB + ((size_t)(n*cinB + (icg - cinA))*HH + gy)*WW + gx);\
                rI[k] = inb ? __ldg(p) : 0.f;                                  \
            }                                                                  \
        }                                                                      \
        {                                                                      \
            int o  = tid / 36;                                                 \
            int ic = (tid / 9) % 4;                                            \
            int t  = tid % 9;                                                  \
            rw0 = w[((size_t)(ocb + o)*cin + ic0_ + ic)*9 + t];                \
            if (tid < 32) {                                                    \
                int idx = tid + 256;                                           \
                int o2  = idx / 36;                                            \
                int ic2 = (idx / 9) % 4;                                       \
                int t2  = idx % 9;                                             \
                rw1 = w[((size_t)(ocb + o2)*cin + ic0_ + ic2)*9 + t2];         \
            }                                                                  \
        }                                                                      \
    }

#define S1_STORE(B)                                                            \
    {                                                                          \
        float* sb = &sIn[B][0][0][0];                                          \
        _Pragma("unroll")                                                      \
        for (int k = 0; k < 19; k++) {                                         \
            int idx = tid + 256*k;                                             \
            if (k < 18 || tid < 144) {                                         \
                int ic  = idx / 1188;                                          \
                int rem = idx - ic*1188;                                       \
                int rr  = rem / 66;                                            \
                int cc  = rem - rr*66;                                         \
                sb[(ic*18 + rr)*68 + cc] = rI[k];                              \
            }                                                                  \
        }                                                                      \
        sW[B][tid] = rw0;                                                      \
        if (tid < 32) sW[B][tid + 256] = rw1;                                  \
    }

    float acc[8][4];
#pragma unroll
    for (int o = 0; o < 8; o++)
#pragma unroll
        for (int j = 0; j < 4; j++) acc[o][j] = 0.f;

    S1_LOAD(0);
    S1_STORE(0);
    __syncthreads();

    for (int c = 0; c < nch; c++) {
        const int b = c & 1;
        if (c + 1 < nch) S1_LOAD((c + 1)*4);

#pragma unroll
        for (int ic = 0; ic < 4; ic++) {
#pragma unroll
            for (int dy = 0; dy < 3; dy++) {
                const float* rp = &sIn[b][ic][ty + dy][4*tx];
                float4 va = *(const float4*)rp;
                float2 vb = *(const float2*)(rp + 4);
                float v[6] = {va.x, va.y, va.z, va.w, vb.x, vb.y};
                const float* wrow = &sW[b][(0*4 + ic)*9 + dy*3];
#pragma unroll
                for (int dx = 0; dx < 3; dx++) {
                    float wv[8];
#pragma unroll
                    for (int o = 0; o < 8; o++) wv[o] = wrow[o*36 + dx];
#pragma unroll
                    for (int j = 0; j < 4; j++) {
                        float xv = v[j + dx];
#pragma unroll
                        for (int o = 0; o < 8; o++)
                            acc[o][j] = fmaf(wv[o], xv, acc[o][j]);
                    }
                }
            }
        }

        if (c + 1 < nch) {
            S1_STORE((c + 1) & 1);
            __syncthreads();
        }
    }

    const int y = y0 + ty;
    const int xb = x0 + 4*tx;
#pragma unroll
    for (int o = 0; o < 8; o++) {
        float bv = bias[ocb + o];
        float v0 = acc[o][0] + bv, v1 = acc[o][1] + bv;
        float v2 = acc[o][2] + bv, v3 = acc[o][3] + bv;
        if (flags & 1) {
            v0 = (v0 >= 0.f) ? v0 : 0.1f*v0;
            v1 = (v1 >= 0.f) ? v1 : 0.1f*v1;
            v2 = (v2 >= 0.f) ? v2 : 0.1f*v2;
            v3 = (v3 >= 0.f) ? v3 : 0.1f*v3;
        }
        float* op = out + ((size_t)(n*cout + ocb + o)*HH + y)*WW + xb;
        if (flags & 2) {
            float4 prev = *(float4*)op;
            prev.x += v0; prev.y += v1; prev.z += v2; prev.w += v3;
            *(float4*)op = prev;
        } else {
            *(float4*)op = make_float4(v0, v1, v2, v3);
        }
    }
#undef S1_LOAD
#undef S1_STORE
}

// ============ pipelined 3x3 stride-2 conv (SAME: pad_lo=0, pad_hi=1) =========
// cin=cout=96. out tile 16x16, 8 oc/thread; 2-ic chunks, double buffered.
__global__ __launch_bounds__(256) void conv3x3_s2v2(
    const float* __restrict__ in, int Hin,
    const float* __restrict__ w, const float* __restrict__ bias,
    float* __restrict__ out, float* __restrict__ out_q, int flags)
{
    const int tid = threadIdx.x;
    const int tx = tid & 15;
    const int ty = tid >> 4;
    const int Hout = Hin >> 1;
    const int tilesX = Hout >> 4;
    const int x0 = (blockIdx.x % tilesX) * 16;
    const int y0 = (blockIdx.x / tilesX) * 16;
    const int ocb = blockIdx.y * 8;
    const int n = blockIdx.z;

    __shared__ float sIn[2][2][33][34];
    __shared__ float sW[2][8*2*9];

    float rI[9];
    float rw0;

#define S2_LOAD(IC0)                                                           \
    {                                                                          \
        const int ic0_ = (IC0);                                                \
        _Pragma("unroll")                                                      \
        for (int k = 0; k < 9; k++) {                                          \
            int idx = tid + 256*k;                                             \
            if (k < 8 || tid < 130) {                                          \
                int ic  = idx / 1089;                                          \
                int rem = idx - ic*1089;                                       \
                int rr  = rem / 33;                                            \
                int cc  = rem - rr*33;                                         \
                int gy = 2*y0 + rr;                                            \
                int gx = 2*x0 + cc;                                            \
                bool inb = (gy < Hin) && (gx < Hin);                           \
                rI[k] = inb ? __ldg(in + ((size_t)(n*NF + ic0_ + ic)*Hin + gy)*Hin + gx) : 0.f; \
            }                                                                  \
        }                                                                      \
        if (tid < 144) {                                                       \
            int o  = tid / 18;                                                 \
            int ic = (tid / 9) % 2;                                            \
            int t  = tid % 9;                                                  \
            rw0 = w[((size_t)(ocb + o)*NF + ic0_ + ic)*9 + t];                 \
        }                                                                      \
    }

#define S2_STORE(B)                                                            \
    {                                                                          \
        float* sb = &sIn[B][0][0][0];                                          \
        _Pragma("unroll")                                                      \
        for (int k = 0; k < 9; k++) {                                          \
            int idx = tid + 256*k;                                             \
            if (k < 8 || tid < 130) {                                          \
                int ic  = idx / 1089;                                          \
                int rem = idx - ic*1089;                                       \
                int rr  = rem / 33;                                            \
                int cc  = rem - rr*33;                                         \
                sb[(ic*33 + rr)*34 + cc] = rI[k];                              \
            }                                                                  \
        }                                                                      \
        if (tid < 144) sW[B][tid] = rw0;                                       \
    }

    float acc[8];
#pragma unroll
    for (int o = 0; o < 8; o++) acc[o] = 0.f;

    S2_LOAD(0);
    S2_STORE(0);
    __syncthreads();

    const int nch = NF/2;
    for (int c = 0; c < nch; c++) {
        const int b = c & 1;
        if (c + 1 < nch) S2_LOAD((c + 1)*2);

#pragma unroll
        for (int ic = 0; ic < 2; ic++) {
#pragma unroll
            for (int dy = 0; dy < 3; dy++) {
#pragma unroll
                for (int dx = 0; dx < 3; dx++) {
                    float xv = sIn[b][ic][2*ty + dy][2*tx + dx];
                    const float* wp = &sW[b][ic*9 + dy*3 + dx];
#pragma unroll
                    for (int o = 0; o < 8; o++)
                        acc[o] = fmaf(wp[o*18], xv, acc[o]);
                }
            }
        }

        if (c + 1 < nch) {
            S2_STORE((c + 1) & 1);
            __syncthreads();
        }
    }

#pragma unroll
    for (int o = 0; o < 8; o++) {
        float v = acc[o] + bias[ocb + o];
        if (flags & 1) v = (v >= 0.f) ? v : 0.1f * v;
        size_t oi = ((size_t)(n*NF + ocb + o)*Hout + (y0 + ty))*Hout + (x0 + tx);
        out[oi] = v;
        if (out_q) out_q[oi] = rintf(v);   // round half to even == jnp.round
    }
#undef S2_LOAD
#undef S2_STORE
}

// ============ 3x3 stride-2 transpose conv (2x upsample), round-1 proven ======
__global__ __launch_bounds__(256) void deconv3x3_x2(
    const float* __restrict__ in, int Hin,
    const float* __restrict__ w, const float* __restrict__ bias,
    float* __restrict__ out, int flags)
{
    const int tid = threadIdx.x;
    const int tx = tid & 15;
    const int ty = tid >> 4;
    const int Hout = Hin * 2;
    const int tilesX = Hout >> 5;
    const int tX = blockIdx.x % tilesX;
    const int tY = blockIdx.x / tilesX;
    const int xin0 = tX * 16, yin0 = tY * 16;
    const int x0o = tX * 32, y0o = tY * 32;
    const int ocb = blockIdx.y * 8;
    const int n = blockIdx.z;

    __shared__ float sIn[4][17][18];
    __shared__ float sW[8][4][9];

    float aEE[8], aEO[8], aOE[8], aOO[8];
#pragma unroll
    for (int o = 0; o < 8; o++) { aEE[o]=0.f; aEO[o]=0.f; aOE[o]=0.f; aOO[o]=0.f; }

    for (int ic0 = 0; ic0 < NF; ic0 += 4) {
        __syncthreads();
        for (int idx = tid; idx < 4*17*17; idx += 256) {
            int ic = idx / (17*17);
            int r  = (idx / 17) % 17;
            int c  = idx % 17;
            int gy = yin0 - 1 + r;
            int gx = xin0 - 1 + c;
            float v = 0.f;
            if ((unsigned)gy < (unsigned)Hin && (unsigned)gx < (unsigned)Hin) {
                v = in[((size_t)(n*NF + ic0 + ic)*Hin + gy)*Hin + gx];
            }
            sIn[ic][r][c] = v;
        }
        for (int idx = tid; idx < 8*4*9; idx += 256) {
            int o  = idx / 36;
            int ic = (idx / 9) % 4;
            int t  = idx % 9;
            sW[o][ic][t] = w[((size_t)(ocb + o)*NF + ic0 + ic)*9 + t];
        }
        __syncthreads();

#pragma unroll
        for (int ic = 0; ic < 4; ic++) {
            float v00 = sIn[ic][ty    ][tx    ];
            float v01 = sIn[ic][ty    ][tx + 1];
            float v10 = sIn[ic][ty + 1][tx    ];
            float v11 = sIn[ic][ty + 1][tx + 1];
#pragma unroll
            for (int o = 0; o < 8; o++) {
                const float* wp = &sW[o][ic][0];
                aEE[o] = fmaf(wp[0], v00, aEE[o]);
                aEE[o] = fmaf(wp[2], v01, aEE[o]);
                aEE[o] = fmaf(wp[6], v10, aEE[o]);
                aEE[o] = fmaf(wp[8], v11, aEE[o]);
                aEO[o] = fmaf(wp[1], v01, aEO[o]);
                aEO[o] = fmaf(wp[7], v11, aEO[o]);
                aOE[o] = fmaf(wp[3], v10, aOE[o]);
                aOE[o] = fmaf(wp[5], v11, aOE[o]);
                aOO[o] = fmaf(wp[4], v11, aOO[o]);
            }
        }
    }

    const int ye = y0o + 2*ty, xe = x0o + 2*tx;
#pragma unroll
    for (int o = 0; o < 8; o++) {
        float bv = bias[ocb + o];
        float vEE = aEE[o] + bv, vEO = aEO[o] + bv, vOE = aOE[o] + bv, vOO = aOO[o] + bv;
        if (flags & 1) {
            vEE = (vEE >= 0.f) ? vEE : 0.1f*vEE;
            vEO = (vEO >= 0.f) ? vEO : 0.1f*vEO;
            vOE = (vOE >= 0.f) ? vOE : 0.1f*vOE;
            vOO = (vOO >= 0.f) ? vOO : 0.1f*vOO;
        }
        size_t base = ((size_t)(n*NF + ocb + o)*Hout + ye)*Hout + xe;
        out[base]            = vEE;
        out[base + 1]        = vEO;
        out[base + Hout]     = vOE;
        out[base + Hout + 1] = vOO;
    }
}

// ============ DCNv1 bilinear sampling ========================================
__global__ __launch_bounds__(256) void dcn_sample(
    const float* __restrict__ ref, const float* __restrict__ off,
    float* __restrict__ S)
{
    int idx = blockIdx.x * 256 + threadIdx.x;
    if (idx >= BN*GD*K2T*HWSZ) return;
    int p = idx & (HWSZ - 1);
    int t = idx >> 14;
    int k = t % 9;  t /= 9;
    int g = t % GD;
    int n = t / GD;
    int y = p >> 7, x = p & 127;

    int offc = (g*9 + k)*2;
    float dy = off[((size_t)(n*2*GD*K2T + offc    ))*HWSZ + p];
    float dx = off[((size_t)(n*2*GD*K2T + offc + 1))*HWSZ + p];
    float py = (float)y + (float)(k/3 - 1) + dy;
    float px = (float)x + (float)(k%3 - 1) + dx;
    float fy = floorf(py), fx = floorf(px);
    float wy = py - fy, wx = px - fx;
    int iy = (int)fy, ix = (int)fx;

    float wgt[4]; int ofs[4];
#pragma unroll
    for (int r = 0; r < 2; r++) {
#pragma unroll
        for (int c = 0; c < 2; c++) {
            int yy = iy + r, xx = ix + c;
            bool val = ((unsigned)yy < (unsigned)HH) && ((unsigned)xx < (unsigned)WW);
            float wv = (r ? wy : 1.f - wy) * (c ? wx : 1.f - wx);
            wgt[r*2 + c] = val ? wv : 0.f;
            ofs[r*2 + c] = val ? (yy*WW + xx) : 0;
        }
    }

    const float* base = ref + (size_t)(n*NF + g*8)*HWSZ;
    float* so = S + ((size_t)(n*NF + g*8)*9 + k)*HWSZ + p;
#pragma unroll
    for (int c = 0; c < 8; c++) {
        const float* bp = base + (size_t)c*HWSZ;
        float s = wgt[0]*bp[ofs[0]] + wgt[1]*bp[ofs[1]]
                + wgt[2]*bp[ofs[2]] + wgt[3]*bp[ofs[3]];
        so[(size_t)c*9*HWSZ] = s;
    }
}

// ============ pipelined 1x1 conv: out[96,HW] = W[96,864] * S[864,HW] =========
// tile: 256 px x 32 oc; thread: 4 px (stride 64) x 8 oc; double buffered.
__global__ __launch_bounds__(256) void conv1x1v2(
    const float* __restrict__ S, const float* __restrict__ w,
    const float* __restrict__ bias, float* __restrict__ out)
{
    const int tid = threadIdx.x;
    const int tpx = tid & 63;
    const int to  = tid >> 6;
    const int p0  = blockIdx.x * 256;
    const int ocb = blockIdx.y * 32;
    const int n   = blockIdx.z;
    const int CIN = NF * K2T;          // 864

    __shared__ float sS[2][8][256];
    __shared__ float sW[2][32*8];

    float rD[8];
    float rw;

#define G1_LOAD(K0)                                                            \
    {                                                                          \
        const int k0_ = (K0);                                                  \
        _Pragma("unroll")                                                      \
        for (int ic = 0; ic < 8; ic++)                                         \
            rD[ic] = __ldg(S + ((size_t)(n*CIN + k0_ + ic))*HWSZ + p0 + tid);  \
        {                                                                      \
            int o = tid >> 3, kk = tid & 7;                                    \
            rw = w[(size_t)(ocb + o)*CIN + k0_ + kk];                          \
        }                                                                      \
    }

#define G1_STORE(B)                                                            \
    {                                                                          \
        _Pragma("unroll")                                                      \
        for (int ic = 0; ic < 8; ic++) sS[B][ic][tid] = rD[ic];                \
        sW[B][tid] = rw;                                                       \
    }

    float acc[8][4];
#pragma unroll
    for (int o = 0; o < 8; o++)
#pragma unroll
        for (int j = 0; j < 4; j++) acc[o][j] = 0.f;

    G1_LOAD(0);
    G1_STORE(0);
    __syncthreads();

    const int nch = CIN/8;
    for (int c = 0; c < nch; c++) {
        const int b = c & 1;
        if (c + 1 < nch) G1_LOAD((c + 1)*8);

#pragma unroll
        for (int k = 0; k < 8; k++) {
            float xv[4];
#pragma unroll
            for (int j = 0; j < 4; j++) xv[j] = sS[b][k][tpx + 64*j];
            float wv[8];
#pragma unroll
            for (int o = 0; o < 8; o++) wv[o] = sW[b][(to*8 + o)*8 + k];
#pragma unroll
            for (int o = 0; o < 8; o++)
#pragma unroll
                for (int j = 0; j < 4; j++)
                    acc[o][j] = fmaf(wv[o], xv[j], acc[o][j]);
        }

        if (c + 1 < nch) {
            G1_STORE((c + 1) & 1);
            __syncthreads();
        }
    }

#pragma unroll
    for (int o = 0; o < 8; o++) {
        float bv = bias[ocb + to*8 + o];
#pragma unroll
        for (int j = 0; j < 4; j++) {
            out[((size_t)(n*NF + ocb + to*8 + o))*HWSZ + p0 + tpx + 64*j] = acc[o][j] + bv;
        }
    }
#undef G1_LOAD
#undef G1_STORE
}

// ------------------------------ launch ---------------------------------------
extern "C" void kernel_launch(void* const* d_in, const int* in_sizes, int n_in,
                              void* d_out, int out_size)
{
    const float* ref   = (const float*)d_in[0];
    const float* inp   = (const float*)d_in[1];
    const float* w_oc1 = (const float*)d_in[2];  const float* b_oc1 = (const float*)d_in[3];
    const float* w_oc3 = (const float*)d_in[4];  const float* b_oc3 = (const float*)d_in[5];
    const float* w_e1  = (const float*)d_in[6];  const float* b_e1  = (const float*)d_in[7];
    const float* w_e2  = (const float*)d_in[8];  const float* b_e2  = (const float*)d_in[9];
    const float* w_d1  = (const float*)d_in[10]; const float* b_d1  = (const float*)d_in[11];
    const float* w_d2  = (const float*)d_in[12]; const float* b_d2  = (const float*)d_in[13];
    const float* w_off = (const float*)d_in[14]; const float* b_off = (const float*)d_in[15];
    const float* w_dcn = (const float*)d_in[16]; const float* b_dcn = (const float*)d_in[17];
    const float* w_c1  = (const float*)d_in[18]; const float* b_c1  = (const float*)d_in[19];
    const float* w_c2  = (const float*)d_in[20]; const float* b_c2  = (const float*)d_in[21];

    float* out  = (float*)d_out;
    float* oL1  = out;                                  // [4,96,128,128]
    float* oEN  = out + (size_t)BN*NF*HWSZ;             // [4,96,32,32]
    float* oQ   = oEN + (size_t)BN*NF*32*32;            // [4,96,32,32]
    float* oDEC = oQ  + (size_t)BN*NF*32*32;            // [4,96,128,128]

    float *t1, *t2, *e1b, *d1b, *offb, *Sb;
    cudaGetSymbolAddress((void**)&t1,   g_t1);
    cudaGetSymbolAddress((void**)&t2,   g_t2);
    cudaGetSymbolAddress((void**)&e1b,  g_e1);
    cudaGetSymbolAddress((void**)&d1b,  g_d1);
    cudaGetSymbolAddress((void**)&offb, g_off);
    cudaGetSymbolAddress((void**)&Sb,   g_S);

    // t = lrelu(conv(concat(ref, inp), oc1)); t = lrelu(conv(t, oc3))
    conv3x3_s1v2<<<dim3(16, 12, BN), 256>>>(ref, NF, inp, NF, w_oc1, b_oc1, t1, NF, 1);
    conv3x3_s1v2<<<dim3(16, 12, BN), 256>>>(t1, NF, nullptr, 0, w_oc3, b_oc3, t2, NF, 1);
    // encoder: e1 (stride2 + lrelu), e2 (stride2) -> en, q=round(en)
    conv3x3_s2v2<<<dim3(16, 12, BN), 256>>>(t2, 128, w_e1, b_e1, e1b, nullptr, 1);
    conv3x3_s2v2<<<dim3(4,  12, BN), 256>>>(e1b, 64, w_e2, b_e2, oEN, oQ, 0);
    // decoder: two 2x transpose convs
    deconv3x3_x2<<<dim3(4,  12, BN), 256>>>(oQ,  32, w_d1, b_d1, d1b, 1);
    deconv3x3_x2<<<dim3(16, 12, BN), 256>>>(d1b, 64, w_d2, b_d2, oDEC, 0);
    // offset head (216 ch)
    conv3x3_s1v2<<<dim3(16, 27, BN), 256>>>(oDEC, NF, nullptr, 0, w_off, b_off, offb, 2*GD*K2T, 0);
    // deformable conv = bilinear sampling + 1x1 GEMM over 864 "channels"
    dcn_sample<<<(BN*GD*K2T*HWSZ)/256, 256>>>(ref, offb, Sb);
    conv1x1v2<<<dim3(HWSZ/256, 3, BN), 256>>>(Sb, w_dcn, b_dcn, oL1);
    // fusion tail: o = lrelu(conv(concat(L1, ref), c1)); o = lrelu(conv(o, c2)); L1 += o
    conv3x3_s1v2<<<dim3(16, 12, BN), 256>>>(oL1, NF, ref, NF, w_c1, b_c1, t1, NF, 1);
    conv3x3_s1v2<<<dim3(16, 12, BN), 256>>>(t1, NF, nullptr, 0, w_c2, b_c2, oL1, NF, 3);
}

// round 7
// speedup vs baseline: 2.1959x; 1.2505x over previous
#include <cuda_runtime.h>
#include <cuda_bf16.h>
#include <math.h>
#include <stdint.h>

#define NF 96
#define GD 12
#define K2T 9
#define BN 4
#define HH 128
#define WW 128
#define HWSZ (HH*WW)

__device__ float g_t1[BN*NF*HWSZ];
__device__ float g_t2[BN*NF*HWSZ];
__device__ float g_e1[BN*NF*64*64];
__device__ float g_d1[BN*NF*64*64];
__device__ float g_off[BN*2*GD*K2T*HWSZ];
__device__ float g_S[BN*NF*K2T*HWSZ];

// ---------------- fp32 pipelined 3x3 s1 conv (oc1, oc3) ----------------------
__global__ __launch_bounds__(256) void conv3x3_s1v2(
    const float* __restrict__ inA, int cinA,
    const float* __restrict__ inB, int cinB,
    const float* __restrict__ w, const float* __restrict__ bias,
    float* __restrict__ out, int cout, int flags)
{
    const int tid = threadIdx.x;
    const int tx = tid & 15, ty = tid >> 4;
    const int x0 = (blockIdx.x & 1) * 64, y0 = (blockIdx.x >> 1) * 16;
    const int ocb = blockIdx.y * 8, n = blockIdx.z;
    const int cin = cinA + cinB, nch = cin >> 2;
    __shared__ float sIn[2][4][18][68];
    __shared__ float sW[2][8*4*9];
    float rI[19]; float rw0, rw1;

#define S1_LOAD(IC0) { const int ic0_=(IC0); \
    _Pragma("unroll") for (int k=0;k<19;k++){ int idx=tid+256*k; \
      if (k<18||tid<144){ int ic=idx/1188; int rem=idx-ic*1188; int rr=rem/66; int cc=rem-rr*66; \
        int gy=y0-1+rr, gx=x0-1+cc; bool inb=((unsigned)gy<(unsigned)HH)&&((unsigned)gx<(unsigned)WW); \
        int icg=ic0_+ic; const float* p=(icg<cinA)?(inA+((size_t)(n*cinA+icg)*HH+gy)*WW+gx):(inB+((size_t)(n*cinB+(icg-cinA))*HH+gy)*WW+gx); \
        rI[k]=inb?__ldg(p):0.f; } } \
    { int o=tid/36, ic=(tid/9)%4, t=tid%9; rw0=w[((size_t)(ocb+o)*cin+ic0_+ic)*9+t]; \
      if (tid<32){ int idx=tid+256; int o2=idx/36, ic2=(idx/9)%4, t2=idx%9; rw1=w[((size_t)(ocb+o2)*cin+ic0_+ic2)*9+t2]; } } }
#define S1_STORE(B) { float* sb=&sIn[B][0][0][0]; \
    _Pragma("unroll") for (int k=0;k<19;k++){ int idx=tid+256*k; \
      if (k<18||tid<144){ int ic=idx/1188; int rem=idx-ic*1188; int rr=rem/66; int cc=rem-rr*66; \
        sb[(ic*18+rr)*68+cc]=rI[k]; } } \
    sW[B][tid]=rw0; if (tid<32) sW[B][tid+256]=rw1; }

    float acc[8][4];
#pragma unroll
    for (int o=0;o<8;o++)
#pragma unroll
      for (int j=0;j<4;j++) acc[o][j]=0.f;
    S1_LOAD(0); S1_STORE(0); __syncthreads();
    for (int c=0;c<nch;c++){
        const int b=c&1;
        if (c+1<nch) S1_LOAD((c+1)*4);
#pragma unroll
        for (int ic=0;ic<4;ic++){
#pragma unroll
            for (int dy=0;dy<3;dy++){
                const float* rp=&sIn[b][ic][ty+dy][4*tx];
                float4 va=*(const float4*)rp; float2 vb=*(const float2*)(rp+4);
                float v[6]={va.x,va.y,va.z,va.w,vb.x,vb.y};
                const float* wrow=&sW[b][ic*9+dy*3];
#pragma unroll
                for (int dx=0;dx<3;dx++){
                    float wv[8];
#pragma unroll
                    for (int o=0;o<8;o++) wv[o]=wrow[o*36+dx];
#pragma unroll
                    for (int j=0;j<4;j++){ float xv=v[j+dx];
#pragma unroll
                        for (int o=0;o<8;o++) acc[o][j]=fmaf(wv[o],xv,acc[o][j]); }
                }
            }
        }
        if (c+1<nch){ S1_STORE((c+1)&1); __syncthreads(); }
    }
    const int y=y0+ty, xb=x0+4*tx;
#pragma unroll
    for (int o=0;o<8;o++){
        float bv=bias[ocb+o];
        float v0=acc[o][0]+bv,v1=acc[o][1]+bv,v2=acc[o][2]+bv,v3=acc[o][3]+bv;
        if (flags&1){ v0=(v0>=0.f)?v0:0.1f*v0; v1=(v1>=0.f)?v1:0.1f*v1; v2=(v2>=0.f)?v2:0.1f*v2; v3=(v3>=0.f)?v3:0.1f*v3; }
        float* op=out+((size_t)(n*cout+ocb+o)*HH+y)*WW+xb;
        if (flags&2){ float4 p=*(float4*)op; p.x+=v0;p.y+=v1;p.z+=v2;p.w+=v3; *(float4*)op=p; }
        else *(float4*)op=make_float4(v0,v1,v2,v3);
    }
#undef S1_LOAD
#undef S1_STORE
}

// ---------------- fp32 pipelined 3x3 s2 conv (e1, e2) ------------------------
__global__ __launch_bounds__(256) void conv3x3_s2v2(
    const float* __restrict__ in, int Hin,
    const float* __restrict__ w, const float* __restrict__ bias,
    float* __restrict__ out, float* __restrict__ out_q, int flags)
{
    const int tid=threadIdx.x, tx=tid&15, ty=tid>>4;
    const int Hout=Hin>>1, tilesX=Hout>>4;
    const int x0=(blockIdx.x%tilesX)*16, y0=(blockIdx.x/tilesX)*16;
    const int ocb=blockIdx.y*8, n=blockIdx.z;
    __shared__ float sIn[2][2][33][34];
    __shared__ float sW[2][8*2*9];
    float rI[9]; float rw0;
#define S2_LOAD(IC0) { const int ic0_=(IC0); \
    _Pragma("unroll") for (int k=0;k<9;k++){ int idx=tid+256*k; \
      if (k<8||tid<130){ int ic=idx/1089; int rem=idx-ic*1089; int rr=rem/33; int cc=rem-rr*33; \
        int gy=2*y0+rr, gx=2*x0+cc; bool inb=(gy<Hin)&&(gx<Hin); \
        rI[k]=inb?__ldg(in+((size_t)(n*NF+ic0_+ic)*Hin+gy)*Hin+gx):0.f; } } \
    if (tid<144){ int o=tid/18, ic=(tid/9)%2, t=tid%9; rw0=w[((size_t)(ocb+o)*NF+ic0_+ic)*9+t]; } }
#define S2_STORE(B) { float* sb=&sIn[B][0][0][0]; \
    _Pragma("unroll") for (int k=0;k<9;k++){ int idx=tid+256*k; \
      if (k<8||tid<130){ int ic=idx/1089; int rem=idx-ic*1089; int rr=rem/33; int cc=rem-rr*33; \
        sb[(ic*33+rr)*34+cc]=rI[k]; } } \
    if (tid<144) sW[B][tid]=rw0; }
    float acc[8];
#pragma unroll
    for (int o=0;o<8;o++) acc[o]=0.f;
    S2_LOAD(0); S2_STORE(0); __syncthreads();
    const int nch=NF/2;
    for (int c=0;c<nch;c++){
        const int b=c&1;
        if (c+1<nch) S2_LOAD((c+1)*2);
#pragma unroll
        for (int ic=0;ic<2;ic++)
#pragma unroll
            for (int dy=0;dy<3;dy++)
#pragma unroll
                for (int dx=0;dx<3;dx++){
                    float xv=sIn[b][ic][2*ty+dy][2*tx+dx];
                    const float* wp=&sW[b][ic*9+dy*3+dx];
#pragma unroll
                    for (int o=0;o<8;o++) acc[o]=fmaf(wp[o*18],xv,acc[o]);
                }
        if (c+1<nch){ S2_STORE((c+1)&1); __syncthreads(); }
    }
#pragma unroll
    for (int o=0;o<8;o++){
        float v=acc[o]+bias[ocb+o];
        if (flags&1) v=(v>=0.f)?v:0.1f*v;
        size_t oi=((size_t)(n*NF+ocb+o)*Hout+(y0+ty))*Hout+(x0+tx);
        out[oi]=v;
        if (out_q) out_q[oi]=rintf(v);
    }
#undef S2_LOAD
#undef S2_STORE
}

// ---------------- fp32 transpose conv (d1, d2) --------------------------------
__global__ __launch_bounds__(256) void deconv3x3_x2(
    const float* __restrict__ in, int Hin,
    const float* __restrict__ w, const float* __restrict__ bias,
    float* __restrict__ out, int flags)
{
    const int tid=threadIdx.x, tx=tid&15, ty=tid>>4;
    const int Hout=Hin*2, tilesX=Hout>>5;
    const int tX=blockIdx.x%tilesX, tY=blockIdx.x/tilesX;
    const int xin0=tX*16, yin0=tY*16, x0o=tX*32, y0o=tY*32;
    const int ocb=blockIdx.y*8, n=blockIdx.z;
    __shared__ float sIn[4][17][18];
    __shared__ float sW[8][4][9];
    float aEE[8],aEO[8],aOE[8],aOO[8];
#pragma unroll
    for (int o=0;o<8;o++){aEE[o]=0.f;aEO[o]=0.f;aOE[o]=0.f;aOO[o]=0.f;}
    for (int ic0=0;ic0<NF;ic0+=4){
        __syncthreads();
        for (int idx=tid;idx<4*17*17;idx+=256){
            int ic=idx/(17*17), r=(idx/17)%17, c=idx%17;
            int gy=yin0-1+r, gx=xin0-1+c;
            float v=0.f;
            if ((unsigned)gy<(unsigned)Hin&&(unsigned)gx<(unsigned)Hin)
                v=in[((size_t)(n*NF+ic0+ic)*Hin+gy)*Hin+gx];
            sIn[ic][r][c]=v;
        }
        for (int idx=tid;idx<8*4*9;idx+=256){
            int o=idx/36, ic=(idx/9)%4, t=idx%9;
            sW[o][ic][t]=w[((size_t)(ocb+o)*NF+ic0+ic)*9+t];
        }
        __syncthreads();
#pragma unroll
        for (int ic=0;ic<4;ic++){
            float v00=sIn[ic][ty][tx], v01=sIn[ic][ty][tx+1];
            float v10=sIn[ic][ty+1][tx], v11=sIn[ic][ty+1][tx+1];
#pragma unroll
            for (int o=0;o<8;o++){
                const float* wp=&sW[o][ic][0];
                aEE[o]=fmaf(wp[0],v00,aEE[o]); aEE[o]=fmaf(wp[2],v01,aEE[o]);
                aEE[o]=fmaf(wp[6],v10,aEE[o]); aEE[o]=fmaf(wp[8],v11,aEE[o]);
                aEO[o]=fmaf(wp[1],v01,aEO[o]); aEO[o]=fmaf(wp[7],v11,aEO[o]);
                aOE[o]=fmaf(wp[3],v10,aOE[o]); aOE[o]=fmaf(wp[5],v11,aOE[o]);
                aOO[o]=fmaf(wp[4],v11,aOO[o]);
            }
        }
    }
    const int ye=y0o+2*ty, xe=x0o+2*tx;
#pragma unroll
    for (int o=0;o<8;o++){
        float bv=bias[ocb+o];
        float vEE=aEE[o]+bv,vEO=aEO[o]+bv,vOE=aOE[o]+bv,vOO=aOO[o]+bv;
        if (flags&1){ vEE=(vEE>=0.f)?vEE:0.1f*vEE; vEO=(vEO>=0.f)?vEO:0.1f*vEO;
                      vOE=(vOE>=0.f)?vOE:0.1f*vOE; vOO=(vOO>=0.f)?vOO:0.1f*vOO; }
        size_t base=((size_t)(n*NF+ocb+o)*Hout+ye)*Hout+xe;
        out[base]=vEE; out[base+1]=vEO; out[base+Hout]=vOE; out[base+Hout+1]=vOO;
    }
}

// ---------------- DCN sampling ------------------------------------------------
__global__ __launch_bounds__(256) void dcn_sample(
    const float* __restrict__ ref, const float* __restrict__ off,
    float* __restrict__ S)
{
    int idx=blockIdx.x*256+threadIdx.x;
    if (idx>=BN*GD*K2T*HWSZ) return;
    int p=idx&(HWSZ-1); int t=idx>>14;
    int k=t%9; t/=9; int g=t%GD, n=t/GD;
    int y=p>>7, x=p&127;
    int offc=(g*9+k)*2;
    float dy=off[((size_t)(n*2*GD*K2T+offc))*HWSZ+p];
    float dx=off[((size_t)(n*2*GD*K2T+offc+1))*HWSZ+p];
    float py=(float)y+(float)(k/3-1)+dy;
    float px=(float)x+(float)(k%3-1)+dx;
    float fy=floorf(py), fx=floorf(px);
    float wy=py-fy, wx=px-fx;
    int iy=(int)fy, ix=(int)fx;
    float wgt[4]; int ofs[4];
#pragma unroll
    for (int r=0;r<2;r++)
#pragma unroll
        for (int c=0;c<2;c++){
            int yy=iy+r, xx=ix+c;
            bool val=((unsigned)yy<(unsigned)HH)&&((unsigned)xx<(unsigned)WW);
            float wv=(r?wy:1.f-wy)*(c?wx:1.f-wx);
            wgt[r*2+c]=val?wv:0.f; ofs[r*2+c]=val?(yy*WW+xx):0;
        }
    const float* base=ref+(size_t)(n*NF+g*8)*HWSZ;
    float* so=S+((size_t)(n*NF+g*8)*9+k)*HWSZ+p;
#pragma unroll
    for (int c=0;c<8;c++){
        const float* bp=base+(size_t)c*HWSZ;
        so[(size_t)c*9*HWSZ]=wgt[0]*bp[ofs[0]]+wgt[1]*bp[ofs[1]]+wgt[2]*bp[ofs[2]]+wgt[3]*bp[ofs[3]];
    }
}

// ================= mma.sync bf16 split-3 implicit GEMM =======================
// CTA: one image row y, M=128 px, N = NF8*16 oc. 8 warps = 4(m)x2(n).
// MODE 0: A = im2row(input, 3x3), K = cin*9.  MODE 1: A = channels, K = cin.
__device__ __forceinline__ void split2(float v0, float v1, uint32_t& hi, uint32_t& lo){
    __nv_bfloat16 h0=__float2bfloat16(v0), h1=__float2bfloat16(v1);
    __nv_bfloat16 l0=__float2bfloat16(v0-__bfloat162float(h0));
    __nv_bfloat16 l1=__float2bfloat16(v1-__bfloat162float(h1));
    hi=((uint32_t)__bfloat16_as_ushort(h1)<<16)|__bfloat16_as_ushort(h0);
    lo=((uint32_t)__bfloat16_as_ushort(l1)<<16)|__bfloat16_as_ushort(l0);
}
#define MMA4(d,a0,a1,a2,a3,b0,b1) \
    asm volatile("mma.sync.aligned.m16n8k16.row.col.f32.bf16.bf16.f32 " \
        "{%0,%1,%2,%3},{%4,%5,%6,%7},{%8,%9},{%0,%1,%2,%3};" \
        : "+f"(d[0]),"+f"(d[1]),"+f"(d[2]),"+f"(d[3]) \
        : "r"(a0),"r"(a1),"r"(a2),"r"(a3),"r"(b0),"r"(b1))

template<int NF8, int MODE>
__global__ __launch_bounds__(256) void gemm_tc(
    const float* __restrict__ inA, int cinA,
    const float* __restrict__ inB, int cinB,
    const float* __restrict__ w, const float* __restrict__ bias,
    float* __restrict__ out, int cout, int flags)
{
    extern __shared__ uint32_t sm[];
    const int Ncta = NF8*16;
    const int AW = 128*18, BW = Ncta*18, PB = 2*AW + 2*BW;
    const int tid=threadIdx.x, lane=tid&31, wid=tid>>5;
    const int g=lane>>2, tig=lane&3;
    const int y=blockIdx.x, n=blockIdx.z;
    const int ocb = blockIdx.y * Ncta;
    const int cin = cinA + cinB;
    const int K = MODE ? cin : cin*9;
    const int nch = K/32;
    const int mIdx = (wid&3)*32, nIdx = (wid>>2)*NF8*8;
    const int apx = tid & 127, ah_ = tid >> 7;

    uint32_t pah[8], pal[8], pbh[NF8], pbl[NF8];

#define FETCH_A(kk, dst) { float vv=0.f; int k_=(kk); \
    if (MODE){ vv = __ldg(inA + ((size_t)(n*cin + k_))*HWSZ + y*WW + apx); } \
    else { int ic_=k_/9, tp_=k_-ic_*9; int gy=y-1+tp_/3, gx=apx-1+tp_%3; \
        if ((unsigned)gy<(unsigned)HH && (unsigned)gx<(unsigned)WW){ \
            const float* p_=(ic_<cinA)? inA+((size_t)(n*cinA+ic_)*HH+gy)*WW+gx \
                                      : inB+((size_t)(n*cinB+(ic_-cinA))*HH+gy)*WW+gx; \
            vv=__ldg(p_); } } \
    dst=vv; }

#define G_LOAD(C) { const int c_=(C); \
    _Pragma("unroll") for (int i=0;i<8;i++){ \
        int k0 = c_*32 + (ah_*8+i)*2; \
        float v0, v1; FETCH_A(k0, v0); FETCH_A(k0+1, v1); \
        split2(v0, v1, pah[i], pal[i]); } \
    _Pragma("unroll") for (int j=0;j<NF8;j++){ \
        int idx = tid + 256*j; int oc = idx>>4, kp = idx&15; \
        int k0 = c_*32 + kp*2; int ocg = ocb + oc; \
        float v0=0.f, v1=0.f; \
        if (ocg < cout){ \
            if (MODE){ v0=__ldg(w+(size_t)ocg*cin+k0); v1=__ldg(w+(size_t)ocg*cin+k0+1); } \
            else { int ic0_=k0/9, t0_=k0-ic0_*9; v0=__ldg(w+((size_t)ocg*cin+ic0_)*9+t0_); \
                   int k1=k0+1; int ic1_=k1/9, t1_=k1-ic1_*9; v1=__ldg(w+((size_t)ocg*cin+ic1_)*9+t1_); } } \
        split2(v0, v1, pbh[j], pbl[j]); } }

#define G_STORE(B) { uint32_t* bb = sm + (B)*PB; \
    _Pragma("unroll") for (int i=0;i<8;i++){ \
        int word = apx*18 + ah_*8 + i; \
        bb[word] = pah[i]; bb[AW + word] = pal[i]; } \
    _Pragma("unroll") for (int j=0;j<NF8;j++){ \
        int idx = tid + 256*j; int oc = idx>>4, kp = idx&15; \
        int word = oc*18 + kp; \
        bb[2*AW + word] = pbh[j]; bb[2*AW + BW + word] = pbl[j]; } }

    float acc[2][NF8][4];
#pragma unroll
    for (int mt=0;mt<2;mt++)
#pragma unroll
        for (int j=0;j<NF8;j++)
#pragma unroll
            for (int q=0;q<4;q++) acc[mt][j][q]=0.f;

    G_LOAD(0); G_STORE(0); __syncthreads();

    for (int c=0;c<nch;c++){
        const int b=c&1;
        if (c+1<nch) G_LOAD(c+1);
        const uint32_t* Ah = sm + b*PB;
        const uint32_t* Al = Ah + AW;
        const uint32_t* Bh = Ah + 2*AW;
        const uint32_t* Bl = Bh + BW;
#pragma unroll
        for (int ks=0;ks<2;ks++){
            uint32_t ha[2][4], la[2][4];
#pragma unroll
            for (int mt=0;mt<2;mt++){
                int r = mIdx + mt*16 + g;
                int w0 = r*18 + ks*8 + tig;
                ha[mt][0]=Ah[w0];        ha[mt][1]=Ah[w0+8*18];
                ha[mt][2]=Ah[w0+4];      ha[mt][3]=Ah[w0+8*18+4];
                la[mt][0]=Al[w0];        la[mt][1]=Al[w0+8*18];
                la[mt][2]=Al[w0+4];      la[mt][3]=Al[w0+8*18+4];
            }
#pragma unroll
            for (int j=0;j<NF8;j++){
                int cc = nIdx + j*8 + g;
                int w0 = cc*18 + ks*8 + tig;
                uint32_t bh0=Bh[w0], bh1=Bh[w0+4];
                uint32_t bl0=Bl[w0], bl1=Bl[w0+4];
#pragma unroll
                for (int mt=0;mt<2;mt++){
                    MMA4(acc[mt][j], ha[mt][0],ha[mt][1],ha[mt][2],ha[mt][3], bh0,bh1);
                    MMA4(acc[mt][j], la[mt][0],la[mt][1],la[mt][2],la[mt][3], bh0,bh1);
                    MMA4(acc[mt][j], ha[mt][0],ha[mt][1],ha[mt][2],ha[mt][3], bl0,bl1);
                }
            }
        }
        if (c+1<nch){ G_STORE((c+1)&1); __syncthreads(); }
    }

    // epilogue: d0:(px,oc0) d1:(px,oc0+1) d2:(px+8,oc0) d3:(px+8,oc0+1)
#pragma unroll
    for (int mt=0;mt<2;mt++){
        int px0 = mIdx + mt*16 + g;
#pragma unroll
        for (int j=0;j<NF8;j++){
            int oc0 = ocb + nIdx + j*8 + 2*tig;
#pragma unroll
            for (int q=0;q<4;q++){
                int oc = oc0 + (q&1);
                int px = px0 + ((q>>1)*8);
                if (oc < cout){
                    float v = acc[mt][j][q] + bias[oc];
                    if (flags&1) v=(v>=0.f)?v:0.1f*v;
                    float* op = out + ((size_t)(n*cout+oc)*HH + y)*WW + px;
                    if (flags&2) *op += v; else *op = v;
                }
            }
        }
    }
#undef FETCH_A
#undef G_LOAD
#undef G_STORE
}

// ------------------------------ launch ---------------------------------------
extern "C" void kernel_launch(void* const* d_in, const int* in_sizes, int n_in,
                              void* d_out, int out_size)
{
    const float* ref   = (const float*)d_in[0];
    const float* inp   = (const float*)d_in[1];
    const float* w_oc1 = (const float*)d_in[2];  const float* b_oc1 = (const float*)d_in[3];
    const float* w_oc3 = (const float*)d_in[4];  const float* b_oc3 = (const float*)d_in[5];
    const float* w_e1  = (const float*)d_in[6];  const float* b_e1  = (const float*)d_in[7];
    const float* w_e2  = (const float*)d_in[8];  const float* b_e2  = (const float*)d_in[9];
    const float* w_d1  = (const float*)d_in[10]; const float* b_d1  = (const float*)d_in[11];
    const float* w_d2  = (const float*)d_in[12]; const float* b_d2  = (const float*)d_in[13];
    const float* w_off = (const float*)d_in[14]; const float* b_off = (const float*)d_in[15];
    const float* w_dcn = (const float*)d_in[16]; const float* b_dcn = (const float*)d_in[17];
    const float* w_c1  = (const float*)d_in[18]; const float* b_c1  = (const float*)d_in[19];
    const float* w_c2  = (const float*)d_in[20]; const float* b_c2  = (const float*)d_in[21];

    float* out  = (float*)d_out;
    float* oL1  = out;
    float* oEN  = out + (size_t)BN*NF*HWSZ;
    float* oQ   = oEN + (size_t)BN*NF*32*32;
    float* oDEC = oQ  + (size_t)BN*NF*32*32;

    float *t1, *t2, *e1b, *d1b, *offb, *Sb;
    cudaGetSymbolAddress((void**)&t1,   g_t1);
    cudaGetSymbolAddress((void**)&t2,   g_t2);
    cudaGetSymbolAddress((void**)&e1b,  g_e1);
    cudaGetSymbolAddress((void**)&d1b,  g_d1);
    cudaGetSymbolAddress((void**)&offb, g_off);
    cudaGetSymbolAddress((void**)&Sb,   g_S);

    // dynamic smem sizes: PB*2 buffers * 4B
    const int smem7 = (2*(2*128*18 + 2*112*18))*4;   // 69120
    const int smem6 = (2*(2*128*18 + 2*96*18))*4;    // 64512
    cudaFuncSetAttribute(gemm_tc<7,0>, cudaFuncAttributeMaxDynamicSharedMemorySize, smem7);
    cudaFuncSetAttribute(gemm_tc<6,0>, cudaFuncAttributeMaxDynamicSharedMemorySize, smem6);
    cudaFuncSetAttribute(gemm_tc<6,1>, cudaFuncAttributeMaxDynamicSharedMemorySize, smem6);

    conv3x3_s1v2<<<dim3(16, 12, BN), 256>>>(ref, NF, inp, NF, w_oc1, b_oc1, t1, NF, 1);
    conv3x3_s1v2<<<dim3(16, 12, BN), 256>>>(t1, NF, nullptr, 0, w_oc3, b_oc3, t2, NF, 1);
    conv3x3_s2v2<<<dim3(16, 12, BN), 256>>>(t2, 128, w_e1, b_e1, e1b, nullptr, 1);
    conv3x3_s2v2<<<dim3(4,  12, BN), 256>>>(e1b, 64, w_e2, b_e2, oEN, oQ, 0);
    deconv3x3_x2<<<dim3(4,  12, BN), 256>>>(oQ,  32, w_d1, b_d1, d1b, 1);
    deconv3x3_x2<<<dim3(16, 12, BN), 256>>>(d1b, 64, w_d2, b_d2, oDEC, 0);
    // offset head (216 ch): 2 oc-blocks of 112
    gemm_tc<7,0><<<dim3(128, 2, BN), 256, smem7>>>(oDEC, NF, nullptr, 0, w_off, b_off, offb, 216, 0);
    dcn_sample<<<(BN*GD*K2T*HWSZ)/256, 256>>>(ref, offb, Sb);
    // DCN 1x1 GEMM over 864 channels
    gemm_tc<6,1><<<dim3(128, 1, BN), 256, smem6>>>(Sb, NF*K2T, nullptr, 0, w_dcn, b_dcn, oL1, NF, 0);
    // fusion tail
    gemm_tc<6,0><<<dim3(128, 1, BN), 256, smem6>>>(oL1, NF, ref, NF, w_c1, b_c1, t1, NF, 1);
    gemm_tc<6,0><<<dim3(128, 1, BN), 256, smem6>>>(t1, NF, nullptr, 0, w_c2, b_c2, oL1, NF, 3);
}